// round 11
// baseline (speedup 1.0000x reference)
#include <cuda_runtime.h>
#include <cstdint>
#include <cstddef>

// ---------------- problem constants (fixed by the dataset) ----------------
#define Bn     16
#define SEQn   256
#define DIMn   1024
#define HEADSn 16
#define DHEADn 64
#define INNERn 1024
#define Mmem   8
#define TXTn   77
#define KVn    (Mmem*SEQn + TXTn)   // 2125
#define MSn    (Mmem*SEQn)          // 2048
#define SCALEf 0.125f               // 64^-0.5

#define ROWS_X   (Bn*SEQn)          // 4096
#define ROWS_C   (Bn*KVn)           // 34000
#define BHn      (Bn*HEADSn)        // 256

// ---------------- scratch (device globals: no allocation allowed) ---------
__device__ float g_Q[ROWS_X * INNERn];
__device__ float g_K[ROWS_C * INNERn];
__device__ float g_V[ROWS_C * INNERn];
__device__ float g_O[ROWS_X * INNERn];
__device__ float g_Wt[4 * DIMn * INNERn];   // [Wtk;Wtv] (2 slots), Wtq, Wto
__device__ float g_cosf[64*64*64];          // cos(freqs), 1MB
__device__ float g_sinf[64*64*64];          // sin(freqs), 1MB

// ---------------- helpers --------------------------------------------------
__device__ __forceinline__ uint32_t smem_u32(const void* p) {
    uint32_t a;
    asm("{ .reg .u64 t; cvta.to.shared.u64 t, %1; cvt.u32.u64 %0, t; }" : "=r"(a) : "l"(p));
    return a;
}
__device__ __forceinline__ float rna_tf32(float x) {
    float y;
    asm("cvt.rna.tf32.f32 %0, %1;" : "=f"(y) : "f"(x));
    return y;
}
__device__ __forceinline__ uint32_t rna_u(uint32_t x) {
    return __float_as_uint(rna_tf32(__uint_as_float(x)));
}
// rotary on a column pair (c even): out0 = t0*cos[fo] - t1*sin[fo];
// out1 = t1*cos[fo+1] + t0*sin[fo+1]   (bias added to both first)
__device__ __forceinline__ void rot_pair(float2& v, float bias,
                                         const float* __restrict__ cf,
                                         const float* __restrict__ sf, int fo) {
    const float t0 = v.x + bias, t1 = v.y + bias;
    v.x = t0 * cf[fo]     - t1 * sf[fo];
    v.y = t1 * cf[fo + 1] + t0 * sf[fo + 1];
}
#define MMA_TF32(d0,d1,d2,d3,a0,a1,a2,a3,b0,b1)                               \
    asm volatile(                                                             \
        "mma.sync.aligned.m16n8k8.row.col.f32.tf32.tf32.f32 "                 \
        "{%0,%1,%2,%3},{%4,%5,%6,%7},{%8,%9},{%0,%1,%2,%3};"                  \
        : "+f"(d0), "+f"(d1), "+f"(d2), "+f"(d3)                              \
        : "r"(a0), "r"(a1), "r"(a2), "r"(a3), "r"(b0), "r"(b1))
#define CP16(dst, src)     asm volatile("cp.async.cg.shared.global [%0], [%1], 16;" :: "r"(dst), "l"(src))
#define CP16P(dst, src, p) asm volatile("cp.async.cg.shared.global [%0], [%1], 16, %2;" :: "r"(dst), "l"(src), "r"(p))
#define CP_COMMIT()        asm volatile("cp.async.commit_group;" ::: "memory")
#define CP_WAIT(n)         asm volatile("cp.async.wait_group %0;" :: "n"(n) : "memory")

// =================== tf32 mma.sync GEMM (projections) ======================
// C[M,N] = A[M,1024] @ Bt[n][k]^T  (Bt K-major; N = gridDim.x*128)
// Tile 128x128x16, 128 threads, 4 warps 2x2, warp tile 64x64.
// A fragments are rna-rounded in-register (A may be raw fp32).
// Weights (Bt) must be pre-rounded.
// SPLIT: col blocks n0>=1024 -> Cv at n0-1024 with rna (V); n0<1024 -> C (K).
// KPOST (with SPLIT): K-half epilogue applies rel-bias + rotary to mem rows.
// QPOST: epilogue applies rotary, then *SCALEf, then rna (pre-staged Q).
#define SA_STR 20   // smem row stride in floats (bank-conflict-free)

template<bool BIAS, bool RND, bool SPLIT, bool KPOST, bool QPOST>
__global__ __launch_bounds__(128, 2)
void gemm_mma(const float* __restrict__ A, const float* __restrict__ Bt,
              float* __restrict__ C, float* __restrict__ Cv,
              const float* __restrict__ bias,
              const float* __restrict__ cf, const float* __restrict__ sf,
              const float* __restrict__ rel_table,
              const int* __restrict__ memidx, const int* __restrict__ cur,
              int M)
{
    __shared__ float As[2][128 * SA_STR];
    __shared__ float Bs[2][128 * SA_STR];

    const int tid  = threadIdx.x;
    const int wid  = tid >> 5, lane = tid & 31;
    const int g    = lane >> 2, tg = lane & 3;
    const int wm   = (wid >> 1) * 64;   // warp m offset
    const int wn   = (wid & 1) * 64;    // warp n offset
    const int m0   = blockIdx.y * 128, n0 = blockIdx.x * 128;

    float d[4][8][4];
#pragma unroll
    for (int i = 0; i < 4; i++)
#pragma unroll
        for (int j = 0; j < 8; j++)
#pragma unroll
            for (int q = 0; q < 4; q++) d[i][j][q] = 0.f;

    auto issue = [&](int buf, int kt) {
        const int k0 = kt * 16;
#pragma unroll
        for (int e = 0; e < 4; e++) {
            int idx = tid + e * 128;        // 0..511
            int row = idx >> 2, c4 = idx & 3;
            int ga = m0 + row;
            int pa = (ga < M) ? 16 : 0;
            if (ga >= M) ga = M - 1;
            uint32_t da = smem_u32(&As[buf][row * SA_STR + c4 * 4]);
            CP16P(da, A + (size_t)ga * 1024u + k0 + c4 * 4, pa);
            uint32_t db = smem_u32(&Bs[buf][row * SA_STR + c4 * 4]);
            CP16(db, Bt + (size_t)(n0 + row) * 1024u + k0 + c4 * 4);
        }
        CP_COMMIT();
    };

    issue(0, 0);
    issue(1, 1);

    for (int kt = 0; kt < 64; kt++) {
        const int buf = kt & 1;
        if (kt < 63) CP_WAIT(1);
        else         CP_WAIT(0);
        __syncthreads();

#pragma unroll
        for (int ks = 0; ks < 2; ks++) {
            uint32_t af[4][4], bf[8][2];
#pragma unroll
            for (int i = 0; i < 4; i++) {
                const float* base = &As[buf][(wm + i * 16) * SA_STR + ks * 8];
                af[i][0] = rna_u(__float_as_uint(base[(g)     * SA_STR + tg]));
                af[i][1] = rna_u(__float_as_uint(base[(g + 8) * SA_STR + tg]));
                af[i][2] = rna_u(__float_as_uint(base[(g)     * SA_STR + tg + 4]));
                af[i][3] = rna_u(__float_as_uint(base[(g + 8) * SA_STR + tg + 4]));
            }
#pragma unroll
            for (int j = 0; j < 8; j++) {
                const float* base = &Bs[buf][(wn + j * 8 + g) * SA_STR + ks * 8];
                bf[j][0] = __float_as_uint(base[tg]);
                bf[j][1] = __float_as_uint(base[tg + 4]);
            }
#pragma unroll
            for (int i = 0; i < 4; i++)
#pragma unroll
                for (int j = 0; j < 8; j++)
                    MMA_TF32(d[i][j][0], d[i][j][1], d[i][j][2], d[i][j][3],
                             af[i][0], af[i][1], af[i][2], af[i][3],
                             bf[j][0], bf[j][1]);
        }
        __syncthreads();
        if (kt + 2 < 64) issue(buf, kt + 2);
    }

    // ---------------- epilogue: warp writes 64x64 --------------------------
    float* Co = C;
    int cb = n0;
    bool dornd = RND;
    bool kblk = false;
    if (SPLIT) {
        if (n0 >= 1024) { Co = Cv; cb = n0 - 1024; dornd = true; }
        else            kblk = true;
    }

    int rs = 0, cs = 0, ts = 0;
    if (KPOST || QPOST) {
        const int cp = cur[0];
        const int ci = cp % 16;
        rs = ci % 4; cs = ci / 4; ts = cp / 16;
    }
    const int hwarp = (n0 + wn) >> 6;   // head index (warp-uniform in K block)

#pragma unroll
    for (int i = 0; i < 4; i++) {
        const int rA = m0 + wm + i * 16 + g;
        const int rB = rA + 8;

        float biasA = 0.f, biasB = 0.f;
        int fobA = 0, fobB = 0;
        bool tA = false, tB = false;
        if (KPOST && kblk) {
            {
                const int b_ = rA / KVn, j = rA - b_ * KVn;
                if (j < MSn) {
                    const int m = j >> 8, jj = j & 255;
                    const int mi = memidx[m], mn = mi % 16;
                    const int rt = mn % 4, ct = mn / 4, tt = mi / 16;
                    const int rel = (rt - rs + 4) * 9 + (ct - cs + 4) + (tt - ts + 4) * 81;
                    biasA = rel_table[rel * HEADSn + hwarp];
                    fobA = (((rt * 16 + (jj >> 4)) << 6) + (ct * 16 + (jj & 15))) * 64;
                    tA = true;
                }
            }
            {
                const int b_ = rB / KVn, j = rB - b_ * KVn;
                if (j < MSn) {
                    const int m = j >> 8, jj = j & 255;
                    const int mi = memidx[m], mn = mi % 16;
                    const int rt = mn % 4, ct = mn / 4, tt = mi / 16;
                    const int rel = (rt - rs + 4) * 9 + (ct - cs + 4) + (tt - ts + 4) * 81;
                    biasB = rel_table[rel * HEADSn + hwarp];
                    fobB = (((rt * 16 + (jj >> 4)) << 6) + (ct * 16 + (jj & 15))) * 64;
                    tB = true;
                }
            }
        }
        if (QPOST) {
            { const int s = rA & 255;
              fobA = (((rs * 16 + (s >> 4)) << 6) + (cs * 16 + (s & 15))) * 64; tA = true; }
            { const int s = rB & 255;
              fobB = (((rs * 16 + (s >> 4)) << 6) + (cs * 16 + (s & 15))) * 64; tB = true; }
        }

#pragma unroll
        for (int j = 0; j < 8; j++) {
            const int c  = cb + wn + j * 8 + tg * 2;
            const int d0 = (wn + j * 8 + tg * 2) & 63;
            float2 v0 = make_float2(d[i][j][0], d[i][j][1]);
            float2 v1 = make_float2(d[i][j][2], d[i][j][3]);
            if (BIAS) {
                const float b0 = bias[c], b1 = bias[c + 1];
                v0.x += b0; v0.y += b1; v1.x += b0; v1.y += b1;
            }
            if ((KPOST || QPOST)) {
                if (tA) rot_pair(v0, biasA, cf, sf, fobA + d0);
                if (tB) rot_pair(v1, biasB, cf, sf, fobB + d0);
            }
            if (QPOST) {
                v0.x = rna_tf32(v0.x * SCALEf); v0.y = rna_tf32(v0.y * SCALEf);
                v1.x = rna_tf32(v1.x * SCALEf); v1.y = rna_tf32(v1.y * SCALEf);
            } else if (dornd) {
                v0.x = rna_tf32(v0.x); v0.y = rna_tf32(v0.y);
                v1.x = rna_tf32(v1.x); v1.y = rna_tf32(v1.y);
            }
            if (rA < M) *(float2*)&Co[(size_t)rA * 1024u + c] = v0;
            if (rB < M) *(float2*)&Co[(size_t)rB * 1024u + c] = v1;
        }
    }
}

// =================== fused flash attention (tf32 mma) ======================
// Q in g_Q is already rotated, scaled and rna-rounded: staging is a raw copy.
#define QS_O 0                        // 128 x 68
#define KS_O (QS_O + 128*68)          // 64 x 68
#define VS_O (KS_O + 64*68)           // 64 x 72
#define SS_O (VS_O + 64*72)           // 128 x 68
#define MR_O (SS_O + 128*68)          // 128
#define LR_O (MR_O + 128)             // 128
#define AR_O (LR_O + 128)             // 128
#define FL_SMEM ((AR_O + 128) * 4)    // bytes = 107008

#define NCHUNK ((KVn + 63) / 64)      // 34

__global__ __launch_bounds__(256, 2)
void flash_attn(const float* __restrict__ Q, const float* __restrict__ K,
                const float* __restrict__ V, float* __restrict__ O)
{
    extern __shared__ float sm[];
    const int tid = threadIdx.x;
    const int wid = tid >> 5, lane = tid & 31;
    const int g = lane >> 2, tg = lane & 3;
    const int bh = blockIdx.y, b = bh >> 4, h = bh & 15;
    const int m0 = blockIdx.x * 128;

    const float* Qb = Q + ((size_t)(b * SEQn + m0)) * 1024u + h * 64;
    const float* Kb = K + ((size_t)b * KVn) * 1024u + h * 64;
    const float* Vb = V + ((size_t)b * KVn) * 1024u + h * 64;

    // Q tile: plain copy (already scaled+rotated+rna)
    for (int e = tid; e < 128 * 64; e += 256) {
        int r = e >> 6, c = e & 63;
        sm[QS_O + r * 68 + c] = Qb[(size_t)r * 1024u + c];
    }
    if (tid < 128) { sm[MR_O + tid] = -1e30f; sm[LR_O + tid] = 0.f; }

    float oacc[4][2][4];
#pragma unroll
    for (int i = 0; i < 4; i++)
#pragma unroll
        for (int j = 0; j < 2; j++)
#pragma unroll
            for (int q = 0; q < 4; q++) oacc[i][j][q] = 0.f;

    const int om = (wid >> 2) * 64;   // warp m offset
    const int on = (wid & 3) * 16;    // warp n offset
    __syncthreads();

    for (int t = 0; t < NCHUNK; t++) {
        const int kv0 = t * 64;
        const int rows = (KVn - kv0 < 64) ? (KVn - kv0) : 64;

        // ---- load K,V chunk (64 x 64 f32 each) via cp.async ----
#pragma unroll
        for (int e = 0; e < 4; e++) {
            int idx = tid + e * 256;          // 0..1023
            int r = idx >> 4, c4 = idx & 15;
            int kvr = kv0 + r; if (kvr >= KVn) kvr = KVn - 1;
            const float* sk = Kb + (size_t)kvr * 1024u + c4 * 4;
            uint32_t dk = smem_u32(&sm[KS_O + r * 68 + c4 * 4]);
            CP16(dk, sk);
            const float* sv = Vb + (size_t)kvr * 1024u + c4 * 4;
            uint32_t dv = smem_u32(&sm[VS_O + r * 72 + c4 * 4]);
            CP16(dv, sv);
        }
        CP_COMMIT();
        CP_WAIT(0);
        __syncthreads();

        // ---- S = Qs @ Ks^T  (warp tile 64x16) ----
        float s[4][2][4];
#pragma unroll
        for (int i = 0; i < 4; i++)
#pragma unroll
            for (int j = 0; j < 2; j++)
#pragma unroll
                for (int q = 0; q < 4; q++) s[i][j][q] = 0.f;

#pragma unroll
        for (int ks = 0; ks < 8; ks++) {
            uint32_t af[4][4], bf[2][2];
#pragma unroll
            for (int i = 0; i < 4; i++) {
                const float* base = &sm[QS_O + (om + i * 16) * 68 + ks * 8];
                af[i][0] = __float_as_uint(base[(g)     * 68 + tg]);
                af[i][1] = __float_as_uint(base[(g + 8) * 68 + tg]);
                af[i][2] = __float_as_uint(base[(g)     * 68 + tg + 4]);
                af[i][3] = __float_as_uint(base[(g + 8) * 68 + tg + 4]);
            }
#pragma unroll
            for (int j = 0; j < 2; j++) {
                const float* base = &sm[KS_O + (on + j * 8 + g) * 68 + ks * 8];
                bf[j][0] = __float_as_uint(base[tg]);
                bf[j][1] = __float_as_uint(base[tg + 4]);
            }
#pragma unroll
            for (int i = 0; i < 4; i++)
#pragma unroll
                for (int j = 0; j < 2; j++)
                    MMA_TF32(s[i][j][0], s[i][j][1], s[i][j][2], s[i][j][3],
                             af[i][0], af[i][1], af[i][2], af[i][3],
                             bf[j][0], bf[j][1]);
        }
        // write S fragments to smem
#pragma unroll
        for (int i = 0; i < 4; i++) {
            const int r0 = om + i * 16 + g;
#pragma unroll
            for (int j = 0; j < 2; j++) {
                const int c = on + j * 8 + tg * 2;
                sm[SS_O + r0 * 68 + c]           = s[i][j][0];
                sm[SS_O + r0 * 68 + c + 1]       = s[i][j][1];
                sm[SS_O + (r0 + 8) * 68 + c]     = s[i][j][2];
                sm[SS_O + (r0 + 8) * 68 + c + 1] = s[i][j][3];
            }
        }
        __syncthreads();

        // ---- online softmax: warp handles rows [wid*16, wid*16+16) ----
#pragma unroll 4
        for (int rr = 0; rr < 16; rr++) {
            const int r = wid * 16 + rr;
            const int c0 = lane * 2;
            float v0 = (c0     < rows) ? sm[SS_O + r * 68 + c0]     : -1e30f;
            float v1 = (c0 + 1 < rows) ? sm[SS_O + r * 68 + c0 + 1] : -1e30f;
            float mx = fmaxf(v0, v1);
#pragma unroll
            for (int o = 16; o; o >>= 1) mx = fmaxf(mx, __shfl_xor_sync(~0u, mx, o));
            const float mold = sm[MR_O + r];
            const float mnew = fmaxf(mold, mx);
            float p0 = (c0     < rows) ? rna_tf32(__expf(v0 - mnew)) : 0.f;
            float p1 = (c0 + 1 < rows) ? rna_tf32(__expf(v1 - mnew)) : 0.f;
            sm[SS_O + r * 68 + c0]     = p0;
            sm[SS_O + r * 68 + c0 + 1] = p1;
            float ls = p0 + p1;
#pragma unroll
            for (int o = 16; o; o >>= 1) ls += __shfl_xor_sync(~0u, ls, o);
            if (lane == 0) {
                const float al = __expf(mold - mnew);
                sm[AR_O + r] = al;
                sm[LR_O + r] = sm[LR_O + r] * al + ls;
                sm[MR_O + r] = mnew;
            }
        }
        __syncthreads();

        // ---- rescale O accumulators ----
#pragma unroll
        for (int i = 0; i < 4; i++) {
            const float a0 = sm[AR_O + om + i * 16 + g];
            const float a1 = sm[AR_O + om + i * 16 + g + 8];
#pragma unroll
            for (int j = 0; j < 2; j++) {
                oacc[i][j][0] *= a0; oacc[i][j][1] *= a0;
                oacc[i][j][2] *= a1; oacc[i][j][3] *= a1;
            }
        }

        // ---- O += P @ V ----
#pragma unroll
        for (int ks = 0; ks < 8; ks++) {
            uint32_t af[4][4], bf[2][2];
#pragma unroll
            for (int i = 0; i < 4; i++) {
                const float* base = &sm[SS_O + (om + i * 16) * 68 + ks * 8];
                af[i][0] = __float_as_uint(base[(g)     * 68 + tg]);
                af[i][1] = __float_as_uint(base[(g + 8) * 68 + tg]);
                af[i][2] = __float_as_uint(base[(g)     * 68 + tg + 4]);
                af[i][3] = __float_as_uint(base[(g + 8) * 68 + tg + 4]);
            }
#pragma unroll
            for (int j = 0; j < 2; j++) {
                bf[j][0] = __float_as_uint(sm[VS_O + (ks * 8 + tg)     * 72 + on + j * 8 + g]);
                bf[j][1] = __float_as_uint(sm[VS_O + (ks * 8 + tg + 4) * 72 + on + j * 8 + g]);
            }
#pragma unroll
            for (int i = 0; i < 4; i++)
#pragma unroll
                for (int j = 0; j < 2; j++)
                    MMA_TF32(oacc[i][j][0], oacc[i][j][1], oacc[i][j][2], oacc[i][j][3],
                             af[i][0], af[i][1], af[i][2], af[i][3],
                             bf[j][0], bf[j][1]);
        }
        __syncthreads();
    }

    // ---- epilogue: O / l, rna-round for out-projection ----
    float* Ob = O + ((size_t)(b * SEQn + m0)) * 1024u + h * 64;
#pragma unroll
    for (int i = 0; i < 4; i++) {
        const int r0 = om + i * 16 + g;
        const float li0 = 1.f / sm[LR_O + r0];
        const float li1 = 1.f / sm[LR_O + r0 + 8];
#pragma unroll
        for (int j = 0; j < 2; j++) {
            const int c = on + j * 8 + tg * 2;
            float2 v0 = make_float2(rna_tf32(oacc[i][j][0] * li0), rna_tf32(oacc[i][j][1] * li0));
            float2 v1 = make_float2(rna_tf32(oacc[i][j][2] * li1), rna_tf32(oacc[i][j][3] * li1));
            *(float2*)&Ob[(size_t)r0 * 1024u + c]       = v0;
            *(float2*)&Ob[(size_t)(r0 + 8) * 1024u + c] = v1;
        }
    }
}

// ---------------- weight transpose + tf32 round ---------------------------
__global__ void transpose_1024(const float* __restrict__ W, float* __restrict__ Wt)
{
    __shared__ float t[32][33];
    const int bx = blockIdx.x * 32, by = blockIdx.y * 32;
    const int tx = threadIdx.x, ty = threadIdx.y;
#pragma unroll
    for (int i = 0; i < 4; i++)
        t[ty + i * 8][tx] = W[(size_t)(by + ty + i * 8) * 1024 + bx + tx];
    __syncthreads();
#pragma unroll
    for (int i = 0; i < 4; i++)
        Wt[(size_t)(bx + ty + i * 8) * 1024 + by + tx] = rna_tf32(t[tx][ty + i * 8]);
}

// ---------------- cos/sin tables of freqs ----------------------------------
__global__ void cs_precompute(const float* __restrict__ freqs,
                              float* __restrict__ cf, float* __restrict__ sf)
{
    int i = blockIdx.x * blockDim.x + threadIdx.x;
    if (i < 64*64*64) {
        float v = freqs[i];
        cf[i] = cosf(v);
        sf[i] = sinf(v);
    }
}

// ---------------- host launch ----------------------------------------------
extern "C" void kernel_launch(void* const* d_in, const int* in_sizes, int n_in,
                              void* d_out, int out_size)
{
    const float* x     = (const float*)d_in[0];
    const float* cond  = (const float*)d_in[1];
    const float* freqs = (const float*)d_in[2];
    const float* Wq    = (const float*)d_in[3];
    const float* Wk    = (const float*)d_in[4];
    const float* Wv    = (const float*)d_in[5];
    const float* rel   = (const float*)d_in[6];
    const float* Wo    = (const float*)d_in[7];
    const float* bo    = (const float*)d_in[8];
    const int*   memi  = (const int*)d_in[9];
    const int*   cur   = (const int*)d_in[10];
    float* out = (float*)d_out;

    float *Qb, *Kb, *Vb, *Ob, *Wt, *Cf, *Sf;
    cudaGetSymbolAddress((void**)&Qb, g_Q);
    cudaGetSymbolAddress((void**)&Kb, g_K);
    cudaGetSymbolAddress((void**)&Vb, g_V);
    cudaGetSymbolAddress((void**)&Ob, g_O);
    cudaGetSymbolAddress((void**)&Wt, g_Wt);
    cudaGetSymbolAddress((void**)&Cf, g_cosf);
    cudaGetSymbolAddress((void**)&Sf, g_sinf);

    cudaFuncSetAttribute(flash_attn, cudaFuncAttributeMaxDynamicSharedMemorySize, FL_SMEM);

    // Wt layout: [Wtk (rows 0-1023); Wtv (rows 1024-2047)] | Wtq | Wto
    float* Wtkv = Wt;                               // 2048 x 1024
    float* Wtq  = Wt + 2LL * DIMn * INNERn;
    float* Wto  = Wt + 3LL * DIMn * INNERn;

    // prep: trig tables + weight transposes (pre-rounded)
    cs_precompute<<<(64*64*64 + 255)/256, 256>>>(freqs, Cf, Sf);
    transpose_1024<<<dim3(32,32), dim3(32,8)>>>(Wk, Wtkv);
    transpose_1024<<<dim3(32,32), dim3(32,8)>>>(Wv, Wtkv + (size_t)DIMn * INNERn);
    transpose_1024<<<dim3(32,32), dim3(32,8)>>>(Wq, Wtq);
    transpose_1024<<<dim3(32,32), dim3(32,8)>>>(Wo, Wto);

    // merged K|V projection, A = raw cond (in-reg rna).
    // K half: fused rel-bias + rotary on mem rows.  V half: rna.
    gemm_mma<false,false,true,true,false><<<dim3(16, 266), 128>>>(
        cond, Wtkv, Kb, Vb, nullptr, Cf, Sf, rel, memi, cur, ROWS_C);

    // Q projection, A = raw x; fused rotary + scale + rna in epilogue.
    gemm_mma<false,false,false,false,true><<<dim3(8, 32), 128>>>(
        x, Wtq, Qb, nullptr, nullptr, Cf, Sf, nullptr, nullptr, cur, ROWS_X);

    // fused flash attention (tf32 mma, online softmax), writes rna(O)
    flash_attn<<<dim3(2, BHn), 256, FL_SMEM>>>(Qb, Kb, Vb, Ob);

    // out = O @ Wo + bo
    gemm_mma<true,false,false,false,false><<<dim3(8, 32), 128>>>(
        Ob, Wto, out, nullptr, bo, nullptr, nullptr, nullptr, nullptr, nullptr, ROWS_X);
}

// round 12
// speedup vs baseline: 1.0418x; 1.0418x over previous
#include <cuda_runtime.h>
#include <cstdint>
#include <cstddef>

// ---------------- problem constants (fixed by the dataset) ----------------
#define Bn     16
#define SEQn   256
#define DIMn   1024
#define HEADSn 16
#define DHEADn 64
#define INNERn 1024
#define Mmem   8
#define TXTn   77
#define KVn    (Mmem*SEQn + TXTn)   // 2125
#define MSn    (Mmem*SEQn)          // 2048
#define SCALEf 0.125f               // 64^-0.5

#define ROWS_X   (Bn*SEQn)          // 4096
#define ROWS_C   (Bn*KVn)           // 34000
#define BHn      (Bn*HEADSn)        // 256

// ---------------- scratch (device globals: no allocation allowed) ---------
__device__ float g_Q[ROWS_X * INNERn];
__device__ float g_K[ROWS_C * INNERn];
__device__ float g_V[ROWS_C * INNERn];
__device__ float g_O[ROWS_X * INNERn];
__device__ float g_Wt[4 * DIMn * INNERn];   // [Wtk;Wtv] (2 slots), Wtq, Wto
__device__ float g_Xr[ROWS_X * DIMn];       // rna(x)
__device__ float g_Cr[ROWS_C * DIMn];       // rna(cond)
__device__ float g_cosf[64*64*64];          // cos(freqs), 1MB
__device__ float g_sinf[64*64*64];          // sin(freqs), 1MB

// ---------------- helpers --------------------------------------------------
__device__ __forceinline__ uint32_t smem_u32(const void* p) {
    uint32_t a;
    asm("{ .reg .u64 t; cvta.to.shared.u64 t, %1; cvt.u32.u64 %0, t; }" : "=r"(a) : "l"(p));
    return a;
}
__device__ __forceinline__ float rna_tf32(float x) {
    float y;
    asm("cvt.rna.tf32.f32 %0, %1;" : "=f"(y) : "f"(x));
    return y;
}
// rotary on a column pair (c even): out0 = t0*cos[fo] - t1*sin[fo];
// out1 = t1*cos[fo+1] + t0*sin[fo+1]   (bias added to both first)
__device__ __forceinline__ void rot_pair(float2& v, float bias,
                                         const float* __restrict__ cf,
                                         const float* __restrict__ sf, int fo) {
    const float t0 = v.x + bias, t1 = v.y + bias;
    v.x = t0 * cf[fo]     - t1 * sf[fo];
    v.y = t1 * cf[fo + 1] + t0 * sf[fo + 1];
}
#define MMA_TF32(d0,d1,d2,d3,a0,a1,a2,a3,b0,b1)                               \
    asm volatile(                                                             \
        "mma.sync.aligned.m16n8k8.row.col.f32.tf32.tf32.f32 "                 \
        "{%0,%1,%2,%3},{%4,%5,%6,%7},{%8,%9},{%0,%1,%2,%3};"                  \
        : "+f"(d0), "+f"(d1), "+f"(d2), "+f"(d3)                              \
        : "r"(a0), "r"(a1), "r"(a2), "r"(a3), "r"(b0), "r"(b1))
#define CP16(dst, src)     asm volatile("cp.async.cg.shared.global [%0], [%1], 16;" :: "r"(dst), "l"(src))
#define CP16P(dst, src, p) asm volatile("cp.async.cg.shared.global [%0], [%1], 16, %2;" :: "r"(dst), "l"(src), "r"(p))
#define CP_COMMIT()        asm volatile("cp.async.commit_group;" ::: "memory")
#define CP_WAIT(n)         asm volatile("cp.async.wait_group %0;" :: "n"(n) : "memory")

// =================== tf32 mma.sync GEMM (projections) ======================
// C[M,N] = A[M,1024] @ Bt[n][k]^T  (Bt K-major; N = gridDim.x*128)
// Tile 128x128x16, 128 threads, 4 warps 2x2, warp tile 64x64.
// A and Bt must be pre-rounded (rna). Inner loop identical to R9 (no cvts).
// SPLIT: col blocks n0>=1024 -> Cv at n0-1024 with rna (V); n0<1024 -> C (K).
// KPOST (with SPLIT): K-half epilogue applies rel-bias + rotary to mem rows.
// QPOST: epilogue applies rotary, then *SCALEf, then rna (pre-staged Q).
#define SA_STR 20   // smem row stride in floats (bank-conflict-free)

template<bool BIAS, bool RND, bool SPLIT, bool KPOST, bool QPOST>
__global__ __launch_bounds__(128, 2)
void gemm_mma(const float* __restrict__ A, const float* __restrict__ Bt,
              float* __restrict__ C, float* __restrict__ Cv,
              const float* __restrict__ bias,
              const float* __restrict__ cf, const float* __restrict__ sf,
              const float* __restrict__ rel_table,
              const int* __restrict__ memidx, const int* __restrict__ cur,
              int M)
{
    __shared__ float As[2][128 * SA_STR];
    __shared__ float Bs[2][128 * SA_STR];

    const int tid  = threadIdx.x;
    const int wid  = tid >> 5, lane = tid & 31;
    const int g    = lane >> 2, tg = lane & 3;
    const int wm   = (wid >> 1) * 64;   // warp m offset
    const int wn   = (wid & 1) * 64;    // warp n offset
    const int m0   = blockIdx.y * 128, n0 = blockIdx.x * 128;

    float d[4][8][4];
#pragma unroll
    for (int i = 0; i < 4; i++)
#pragma unroll
        for (int j = 0; j < 8; j++)
#pragma unroll
            for (int q = 0; q < 4; q++) d[i][j][q] = 0.f;

    auto issue = [&](int buf, int kt) {
        const int k0 = kt * 16;
#pragma unroll
        for (int e = 0; e < 4; e++) {
            int idx = tid + e * 128;        // 0..511
            int row = idx >> 2, c4 = idx & 3;
            int ga = m0 + row;
            int pa = (ga < M) ? 16 : 0;
            if (ga >= M) ga = M - 1;
            uint32_t da = smem_u32(&As[buf][row * SA_STR + c4 * 4]);
            CP16P(da, A + (size_t)ga * 1024u + k0 + c4 * 4, pa);
            uint32_t db = smem_u32(&Bs[buf][row * SA_STR + c4 * 4]);
            CP16(db, Bt + (size_t)(n0 + row) * 1024u + k0 + c4 * 4);
        }
        CP_COMMIT();
    };

    issue(0, 0);
    issue(1, 1);

    for (int kt = 0; kt < 64; kt++) {
        const int buf = kt & 1;
        if (kt < 63) CP_WAIT(1);
        else         CP_WAIT(0);
        __syncthreads();

#pragma unroll
        for (int ks = 0; ks < 2; ks++) {
            uint32_t af[4][4], bf[8][2];
#pragma unroll
            for (int i = 0; i < 4; i++) {
                const float* base = &As[buf][(wm + i * 16) * SA_STR + ks * 8];
                af[i][0] = __float_as_uint(base[(g)     * SA_STR + tg]);
                af[i][1] = __float_as_uint(base[(g + 8) * SA_STR + tg]);
                af[i][2] = __float_as_uint(base[(g)     * SA_STR + tg + 4]);
                af[i][3] = __float_as_uint(base[(g + 8) * SA_STR + tg + 4]);
            }
#pragma unroll
            for (int j = 0; j < 8; j++) {
                const float* base = &Bs[buf][(wn + j * 8 + g) * SA_STR + ks * 8];
                bf[j][0] = __float_as_uint(base[tg]);
                bf[j][1] = __float_as_uint(base[tg + 4]);
            }
#pragma unroll
            for (int i = 0; i < 4; i++)
#pragma unroll
                for (int j = 0; j < 8; j++)
                    MMA_TF32(d[i][j][0], d[i][j][1], d[i][j][2], d[i][j][3],
                             af[i][0], af[i][1], af[i][2], af[i][3],
                             bf[j][0], bf[j][1]);
        }
        __syncthreads();
        if (kt + 2 < 64) issue(buf, kt + 2);
    }

    // ---------------- epilogue: warp writes 64x64 --------------------------
    float* Co = C;
    int cb = n0;
    bool dornd = RND;
    bool kblk = false;
    if (SPLIT) {
        if (n0 >= 1024) { Co = Cv; cb = n0 - 1024; dornd = true; }
        else            kblk = true;
    }

    int rs = 0, cs = 0, ts = 0;
    if (KPOST || QPOST) {
        const int cp = cur[0];
        const int ci = cp % 16;
        rs = ci % 4; cs = ci / 4; ts = cp / 16;
    }
    const int hwarp = (n0 + wn) >> 6;   // head index (warp-uniform in K block)

#pragma unroll
    for (int i = 0; i < 4; i++) {
        const int rA = m0 + wm + i * 16 + g;
        const int rB = rA + 8;

        float biasA = 0.f, biasB = 0.f;
        int fobA = 0, fobB = 0;
        bool tA = false, tB = false;
        if (KPOST && kblk) {
            {
                const int b_ = rA / KVn, j = rA - b_ * KVn;
                if (j < MSn) {
                    const int m = j >> 8, jj = j & 255;
                    const int mi = memidx[m], mn = mi % 16;
                    const int rt = mn % 4, ct = mn / 4, tt = mi / 16;
                    const int rel = (rt - rs + 4) * 9 + (ct - cs + 4) + (tt - ts + 4) * 81;
                    biasA = rel_table[rel * HEADSn + hwarp];
                    fobA = (((rt * 16 + (jj >> 4)) << 6) + (ct * 16 + (jj & 15))) * 64;
                    tA = true;
                }
            }
            {
                const int b_ = rB / KVn, j = rB - b_ * KVn;
                if (j < MSn) {
                    const int m = j >> 8, jj = j & 255;
                    const int mi = memidx[m], mn = mi % 16;
                    const int rt = mn % 4, ct = mn / 4, tt = mi / 16;
                    const int rel = (rt - rs + 4) * 9 + (ct - cs + 4) + (tt - ts + 4) * 81;
                    biasB = rel_table[rel * HEADSn + hwarp];
                    fobB = (((rt * 16 + (jj >> 4)) << 6) + (ct * 16 + (jj & 15))) * 64;
                    tB = true;
                }
            }
        }
        if (QPOST) {
            { const int s = rA & 255;
              fobA = (((rs * 16 + (s >> 4)) << 6) + (cs * 16 + (s & 15))) * 64; tA = true; }
            { const int s = rB & 255;
              fobB = (((rs * 16 + (s >> 4)) << 6) + (cs * 16 + (s & 15))) * 64; tB = true; }
        }

#pragma unroll
        for (int j = 0; j < 8; j++) {
            const int c  = cb + wn + j * 8 + tg * 2;
            const int d0 = (wn + j * 8 + tg * 2) & 63;
            float2 v0 = make_float2(d[i][j][0], d[i][j][1]);
            float2 v1 = make_float2(d[i][j][2], d[i][j][3]);
            if (BIAS) {
                const float b0 = bias[c], b1 = bias[c + 1];
                v0.x += b0; v0.y += b1; v1.x += b0; v1.y += b1;
            }
            if ((KPOST || QPOST)) {
                if (tA) rot_pair(v0, biasA, cf, sf, fobA + d0);
                if (tB) rot_pair(v1, biasB, cf, sf, fobB + d0);
            }
            if (QPOST) {
                v0.x = rna_tf32(v0.x * SCALEf); v0.y = rna_tf32(v0.y * SCALEf);
                v1.x = rna_tf32(v1.x * SCALEf); v1.y = rna_tf32(v1.y * SCALEf);
            } else if (dornd) {
                v0.x = rna_tf32(v0.x); v0.y = rna_tf32(v0.y);
                v1.x = rna_tf32(v1.x); v1.y = rna_tf32(v1.y);
            }
            if (rA < M) *(float2*)&Co[(size_t)rA * 1024u + c] = v0;
            if (rB < M) *(float2*)&Co[(size_t)rB * 1024u + c] = v1;
        }
    }
}

// =================== fused flash attention (tf32 mma) ======================
// Q in g_Q is already rotated, scaled and rna-rounded: staging is a raw copy.
#define QS_O 0                        // 128 x 68
#define KS_O (QS_O + 128*68)          // 64 x 68
#define VS_O (KS_O + 64*68)           // 64 x 72
#define SS_O (VS_O + 64*72)           // 128 x 68
#define MR_O (SS_O + 128*68)          // 128
#define LR_O (MR_O + 128)             // 128
#define AR_O (LR_O + 128)             // 128
#define FL_SMEM ((AR_O + 128) * 4)    // bytes = 107008

#define NCHUNK ((KVn + 63) / 64)      // 34

__global__ __launch_bounds__(256, 2)
void flash_attn(const float* __restrict__ Q, const float* __restrict__ K,
                const float* __restrict__ V, float* __restrict__ O)
{
    extern __shared__ float sm[];
    const int tid = threadIdx.x;
    const int wid = tid >> 5, lane = tid & 31;
    const int g = lane >> 2, tg = lane & 3;
    const int bh = blockIdx.y, b = bh >> 4, h = bh & 15;
    const int m0 = blockIdx.x * 128;

    const float* Qb = Q + ((size_t)(b * SEQn + m0)) * 1024u + h * 64;
    const float* Kb = K + ((size_t)b * KVn) * 1024u + h * 64;
    const float* Vb = V + ((size_t)b * KVn) * 1024u + h * 64;

    // Q tile: plain copy (already scaled+rotated+rna)
    for (int e = tid; e < 128 * 64; e += 256) {
        int r = e >> 6, c = e & 63;
        sm[QS_O + r * 68 + c] = Qb[(size_t)r * 1024u + c];
    }
    if (tid < 128) { sm[MR_O + tid] = -1e30f; sm[LR_O + tid] = 0.f; }

    float oacc[4][2][4];
#pragma unroll
    for (int i = 0; i < 4; i++)
#pragma unroll
        for (int j = 0; j < 2; j++)
#pragma unroll
            for (int q = 0; q < 4; q++) oacc[i][j][q] = 0.f;

    const int om = (wid >> 2) * 64;   // warp m offset
    const int on = (wid & 3) * 16;    // warp n offset
    __syncthreads();

    for (int t = 0; t < NCHUNK; t++) {
        const int kv0 = t * 64;
        const int rows = (KVn - kv0 < 64) ? (KVn - kv0) : 64;

        // ---- load K,V chunk (64 x 64 f32 each) via cp.async ----
#pragma unroll
        for (int e = 0; e < 4; e++) {
            int idx = tid + e * 256;          // 0..1023
            int r = idx >> 4, c4 = idx & 15;
            int kvr = kv0 + r; if (kvr >= KVn) kvr = KVn - 1;
            const float* sk = Kb + (size_t)kvr * 1024u + c4 * 4;
            uint32_t dk = smem_u32(&sm[KS_O + r * 68 + c4 * 4]);
            CP16(dk, sk);
            const float* sv = Vb + (size_t)kvr * 1024u + c4 * 4;
            uint32_t dv = smem_u32(&sm[VS_O + r * 72 + c4 * 4]);
            CP16(dv, sv);
        }
        CP_COMMIT();
        CP_WAIT(0);
        __syncthreads();

        // ---- S = Qs @ Ks^T  (warp tile 64x16) ----
        float s[4][2][4];
#pragma unroll
        for (int i = 0; i < 4; i++)
#pragma unroll
            for (int j = 0; j < 2; j++)
#pragma unroll
                for (int q = 0; q < 4; q++) s[i][j][q] = 0.f;

#pragma unroll
        for (int ks = 0; ks < 8; ks++) {
            uint32_t af[4][4], bf[2][2];
#pragma unroll
            for (int i = 0; i < 4; i++) {
                const float* base = &sm[QS_O + (om + i * 16) * 68 + ks * 8];
                af[i][0] = __float_as_uint(base[(g)     * 68 + tg]);
                af[i][1] = __float_as_uint(base[(g + 8) * 68 + tg]);
                af[i][2] = __float_as_uint(base[(g)     * 68 + tg + 4]);
                af[i][3] = __float_as_uint(base[(g + 8) * 68 + tg + 4]);
            }
#pragma unroll
            for (int j = 0; j < 2; j++) {
                const float* base = &sm[KS_O + (on + j * 8 + g) * 68 + ks * 8];
                bf[j][0] = __float_as_uint(base[tg]);
                bf[j][1] = __float_as_uint(base[tg + 4]);
            }
#pragma unroll
            for (int i = 0; i < 4; i++)
#pragma unroll
                for (int j = 0; j < 2; j++)
                    MMA_TF32(s[i][j][0], s[i][j][1], s[i][j][2], s[i][j][3],
                             af[i][0], af[i][1], af[i][2], af[i][3],
                             bf[j][0], bf[j][1]);
        }
        // write S fragments to smem
#pragma unroll
        for (int i = 0; i < 4; i++) {
            const int r0 = om + i * 16 + g;
#pragma unroll
            for (int j = 0; j < 2; j++) {
                const int c = on + j * 8 + tg * 2;
                sm[SS_O + r0 * 68 + c]           = s[i][j][0];
                sm[SS_O + r0 * 68 + c + 1]       = s[i][j][1];
                sm[SS_O + (r0 + 8) * 68 + c]     = s[i][j][2];
                sm[SS_O + (r0 + 8) * 68 + c + 1] = s[i][j][3];
            }
        }
        __syncthreads();

        // ---- online softmax: warp handles rows [wid*16, wid*16+16) ----
#pragma unroll 4
        for (int rr = 0; rr < 16; rr++) {
            const int r = wid * 16 + rr;
            const int c0 = lane * 2;
            float v0 = (c0     < rows) ? sm[SS_O + r * 68 + c0]     : -1e30f;
            float v1 = (c0 + 1 < rows) ? sm[SS_O + r * 68 + c0 + 1] : -1e30f;
            float mx = fmaxf(v0, v1);
#pragma unroll
            for (int o = 16; o; o >>= 1) mx = fmaxf(mx, __shfl_xor_sync(~0u, mx, o));
            const float mold = sm[MR_O + r];
            const float mnew = fmaxf(mold, mx);
            float p0 = (c0     < rows) ? rna_tf32(__expf(v0 - mnew)) : 0.f;
            float p1 = (c0 + 1 < rows) ? rna_tf32(__expf(v1 - mnew)) : 0.f;
            sm[SS_O + r * 68 + c0]     = p0;
            sm[SS_O + r * 68 + c0 + 1] = p1;
            float ls = p0 + p1;
#pragma unroll
            for (int o = 16; o; o >>= 1) ls += __shfl_xor_sync(~0u, ls, o);
            if (lane == 0) {
                const float al = __expf(mold - mnew);
                sm[AR_O + r] = al;
                sm[LR_O + r] = sm[LR_O + r] * al + ls;
                sm[MR_O + r] = mnew;
            }
        }
        __syncthreads();

        // ---- rescale O accumulators ----
#pragma unroll
        for (int i = 0; i < 4; i++) {
            const float a0 = sm[AR_O + om + i * 16 + g];
            const float a1 = sm[AR_O + om + i * 16 + g + 8];
#pragma unroll
            for (int j = 0; j < 2; j++) {
                oacc[i][j][0] *= a0; oacc[i][j][1] *= a0;
                oacc[i][j][2] *= a1; oacc[i][j][3] *= a1;
            }
        }

        // ---- O += P @ V ----
#pragma unroll
        for (int ks = 0; ks < 8; ks++) {
            uint32_t af[4][4], bf[2][2];
#pragma unroll
            for (int i = 0; i < 4; i++) {
                const float* base = &sm[SS_O + (om + i * 16) * 68 + ks * 8];
                af[i][0] = __float_as_uint(base[(g)     * 68 + tg]);
                af[i][1] = __float_as_uint(base[(g + 8) * 68 + tg]);
                af[i][2] = __float_as_uint(base[(g)     * 68 + tg + 4]);
                af[i][3] = __float_as_uint(base[(g + 8) * 68 + tg + 4]);
            }
#pragma unroll
            for (int j = 0; j < 2; j++) {
                bf[j][0] = __float_as_uint(sm[VS_O + (ks * 8 + tg)     * 72 + on + j * 8 + g]);
                bf[j][1] = __float_as_uint(sm[VS_O + (ks * 8 + tg + 4) * 72 + on + j * 8 + g]);
            }
#pragma unroll
            for (int i = 0; i < 4; i++)
#pragma unroll
                for (int j = 0; j < 2; j++)
                    MMA_TF32(oacc[i][j][0], oacc[i][j][1], oacc[i][j][2], oacc[i][j][3],
                             af[i][0], af[i][1], af[i][2], af[i][3],
                             bf[j][0], bf[j][1]);
        }
        __syncthreads();
    }

    // ---- epilogue: O / l, rna-round for out-projection ----
    float* Ob = O + ((size_t)(b * SEQn + m0)) * 1024u + h * 64;
#pragma unroll
    for (int i = 0; i < 4; i++) {
        const int r0 = om + i * 16 + g;
        const float li0 = 1.f / sm[LR_O + r0];
        const float li1 = 1.f / sm[LR_O + r0 + 8];
#pragma unroll
        for (int j = 0; j < 2; j++) {
            const int c = on + j * 8 + tg * 2;
            float2 v0 = make_float2(rna_tf32(oacc[i][j][0] * li0), rna_tf32(oacc[i][j][1] * li0));
            float2 v1 = make_float2(rna_tf32(oacc[i][j][2] * li1), rna_tf32(oacc[i][j][3] * li1));
            *(float2*)&Ob[(size_t)r0 * 1024u + c]       = v0;
            *(float2*)&Ob[(size_t)(r0 + 8) * 1024u + c] = v1;
        }
    }
}

// ---------------- weight transpose + tf32 round ---------------------------
__global__ void transpose_1024(const float* __restrict__ W, float* __restrict__ Wt)
{
    __shared__ float t[32][33];
    const int bx = blockIdx.x * 32, by = blockIdx.y * 32;
    const int tx = threadIdx.x, ty = threadIdx.y;
#pragma unroll
    for (int i = 0; i < 4; i++)
        t[ty + i * 8][tx] = W[(size_t)(by + ty + i * 8) * 1024 + bx + tx];
    __syncthreads();
#pragma unroll
    for (int i = 0; i < 4; i++)
        Wt[(size_t)(bx + ty + i * 8) * 1024 + by + tx] = rna_tf32(t[tx][ty + i * 8]);
}

// ---------------- tf32 rounding copy ---------------------------------------
__global__ void round_copy(const float4* __restrict__ in, float4* __restrict__ out, int n4)
{
    int i = blockIdx.x * blockDim.x + threadIdx.x;
    if (i < n4) {
        float4 v = in[i];
        v.x = rna_tf32(v.x); v.y = rna_tf32(v.y);
        v.z = rna_tf32(v.z); v.w = rna_tf32(v.w);
        out[i] = v;
    }
}

// ---------------- cos/sin tables of freqs ----------------------------------
__global__ void cs_precompute(const float* __restrict__ freqs,
                              float* __restrict__ cf, float* __restrict__ sf)
{
    int i = blockIdx.x * blockDim.x + threadIdx.x;
    if (i < 64*64*64) {
        float v = freqs[i];
        cf[i] = cosf(v);
        sf[i] = sinf(v);
    }
}

// ---------------- host launch ----------------------------------------------
extern "C" void kernel_launch(void* const* d_in, const int* in_sizes, int n_in,
                              void* d_out, int out_size)
{
    const float* x     = (const float*)d_in[0];
    const float* cond  = (const float*)d_in[1];
    const float* freqs = (const float*)d_in[2];
    const float* Wq    = (const float*)d_in[3];
    const float* Wk    = (const float*)d_in[4];
    const float* Wv    = (const float*)d_in[5];
    const float* rel   = (const float*)d_in[6];
    const float* Wo    = (const float*)d_in[7];
    const float* bo    = (const float*)d_in[8];
    const int*   memi  = (const int*)d_in[9];
    const int*   cur   = (const int*)d_in[10];
    float* out = (float*)d_out;

    float *Qb, *Kb, *Vb, *Ob, *Wt, *Xr, *Cr, *Cf, *Sf;
    cudaGetSymbolAddress((void**)&Qb, g_Q);
    cudaGetSymbolAddress((void**)&Kb, g_K);
    cudaGetSymbolAddress((void**)&Vb, g_V);
    cudaGetSymbolAddress((void**)&Ob, g_O);
    cudaGetSymbolAddress((void**)&Wt, g_Wt);
    cudaGetSymbolAddress((void**)&Xr, g_Xr);
    cudaGetSymbolAddress((void**)&Cr, g_Cr);
    cudaGetSymbolAddress((void**)&Cf, g_cosf);
    cudaGetSymbolAddress((void**)&Sf, g_sinf);

    cudaFuncSetAttribute(flash_attn, cudaFuncAttributeMaxDynamicSharedMemorySize, FL_SMEM);

    // Wt layout: [Wtk (rows 0-1023); Wtv (rows 1024-2047)] | Wtq | Wto
    float* Wtkv = Wt;                               // 2048 x 1024
    float* Wtq  = Wt + 2LL * DIMn * INNERn;
    float* Wto  = Wt + 3LL * DIMn * INNERn;

    // prep: rounding copies, trig tables, weight transposes (pre-rounded)
    round_copy<<<(ROWS_X*DIMn/4 + 255)/256, 256>>>((const float4*)x,    (float4*)Xr, ROWS_X*DIMn/4);
    round_copy<<<(ROWS_C*DIMn/4 + 255)/256, 256>>>((const float4*)cond, (float4*)Cr, ROWS_C*DIMn/4);
    cs_precompute<<<(64*64*64 + 255)/256, 256>>>(freqs, Cf, Sf);
    transpose_1024<<<dim3(32,32), dim3(32,8)>>>(Wk, Wtkv);
    transpose_1024<<<dim3(32,32), dim3(32,8)>>>(Wv, Wtkv + (size_t)DIMn * INNERn);
    transpose_1024<<<dim3(32,32), dim3(32,8)>>>(Wq, Wtq);
    transpose_1024<<<dim3(32,32), dim3(32,8)>>>(Wo, Wto);

    // merged K|V projection (A pre-rounded).
    // K half: fused rel-bias + rotary on mem rows.  V half: rna.
    gemm_mma<false,false,true,true,false><<<dim3(16, 266), 128>>>(
        Cr, Wtkv, Kb, Vb, nullptr, Cf, Sf, rel, memi, cur, ROWS_C);

    // Q projection (A pre-rounded); fused rotary + scale + rna in epilogue.
    gemm_mma<false,false,false,false,true><<<dim3(8, 32), 128>>>(
        Xr, Wtq, Qb, nullptr, nullptr, Cf, Sf, nullptr, nullptr, cur, ROWS_X);

    // fused flash attention (tf32 mma, online softmax), writes rna(O)
    flash_attn<<<dim3(2, BHn), 256, FL_SMEM>>>(Qb, Kb, Vb, Ob);

    // out = O @ Wo + bo
    gemm_mma<true,false,false,false,false><<<dim3(8, 32), 128>>>(
        Ob, Wto, out, nullptr, bo, nullptr, nullptr, nullptr, nullptr, nullptr, ROWS_X);
}

// round 13
// speedup vs baseline: 1.3514x; 1.2971x over previous
#include <cuda_runtime.h>
#include <cuda_fp16.h>
#include <cstdint>
#include <cstddef>

// ---------------- problem constants (fixed by the dataset) ----------------
#define Bn     16
#define SEQn   256
#define DIMn   1024
#define HEADSn 16
#define DHEADn 64
#define INNERn 1024
#define Mmem   8
#define TXTn   77
#define KVn    (Mmem*SEQn + TXTn)   // 2125
#define MSn    (Mmem*SEQn)          // 2048
#define SCALEf 0.125f               // 64^-0.5

#define ROWS_X   (Bn*SEQn)          // 4096
#define ROWS_C   (Bn*KVn)           // 34000
#define BHn      (Bn*HEADSn)        // 256

// ---------------- scratch (device globals: no allocation allowed) ---------
__device__ float  g_Q[ROWS_X * INNERn];
__device__ float  g_K[ROWS_C * INNERn];
__device__ float  g_V[ROWS_C * INNERn];
__device__ float  g_O[ROWS_X * INNERn];
__device__ float  g_Wt[2 * DIMn * INNERn];     // Wtq, Wto (tf32 path)
__device__ __half g_Whkv[2 * DIMn * INNERn];   // [Wtk;Wtv] K-major halves
__device__ __half g_Ch[ROWS_C * DIMn];         // half(cond)
__device__ float  g_Xr[ROWS_X * DIMn];         // rna(x)
__device__ float  g_cosf[64*64*64];
__device__ float  g_sinf[64*64*64];

// ---------------- helpers --------------------------------------------------
__device__ __forceinline__ uint32_t smem_u32(const void* p) {
    uint32_t a;
    asm("{ .reg .u64 t; cvta.to.shared.u64 t, %1; cvt.u32.u64 %0, t; }" : "=r"(a) : "l"(p));
    return a;
}
__device__ __forceinline__ float rna_tf32(float x) {
    float y;
    asm("cvt.rna.tf32.f32 %0, %1;" : "=f"(y) : "f"(x));
    return y;
}
__device__ __forceinline__ void rot_pair(float2& v, float bias,
                                         const float* __restrict__ cf,
                                         const float* __restrict__ sf, int fo) {
    const float t0 = v.x + bias, t1 = v.y + bias;
    v.x = t0 * cf[fo]     - t1 * sf[fo];
    v.y = t1 * cf[fo + 1] + t0 * sf[fo + 1];
}
#define MMA_TF32(d0,d1,d2,d3,a0,a1,a2,a3,b0,b1)                               \
    asm volatile(                                                             \
        "mma.sync.aligned.m16n8k8.row.col.f32.tf32.tf32.f32 "                 \
        "{%0,%1,%2,%3},{%4,%5,%6,%7},{%8,%9},{%0,%1,%2,%3};"                  \
        : "+f"(d0), "+f"(d1), "+f"(d2), "+f"(d3)                              \
        : "r"(a0), "r"(a1), "r"(a2), "r"(a3), "r"(b0), "r"(b1))
#define MMA_F16(d0,d1,d2,d3,a0,a1,a2,a3,b0,b1)                                \
    asm volatile(                                                             \
        "mma.sync.aligned.m16n8k16.row.col.f32.f16.f16.f32 "                  \
        "{%0,%1,%2,%3},{%4,%5,%6,%7},{%8,%9},{%0,%1,%2,%3};"                  \
        : "+f"(d0), "+f"(d1), "+f"(d2), "+f"(d3)                              \
        : "r"(a0), "r"(a1), "r"(a2), "r"(a3), "r"(b0), "r"(b1))
#define CP16(dst, src)     asm volatile("cp.async.cg.shared.global [%0], [%1], 16;" :: "r"(dst), "l"(src))
#define CP16P(dst, src, p) asm volatile("cp.async.cg.shared.global [%0], [%1], 16, %2;" :: "r"(dst), "l"(src), "r"(p))
#define CP_COMMIT()        asm volatile("cp.async.commit_group;" ::: "memory")
#define CP_WAIT(n)         asm volatile("cp.async.wait_group %0;" :: "n"(n) : "memory")

// =================== fp16 mma GEMM: merged K|V projection ==================
// C[M,2048] = A[M,1024]@[Wtk;Wtv]^T.  A, Bt in half (rn-rounded), accum fp32.
// Tile 128x128x32 (BK=32 halves = 64B/row), 128 thr, 4 warps 2x2, warp 64x64.
// Same double-buffer control flow as the proven tf32 kernel.
// Epilogue: n0<1024 -> K with rel-bias + rotary on mem rows;
//           n0>=1024 -> V at n0-1024 with rna.
#define HSTR 40   // smem row stride in halves (80B): banks 20r+tg all distinct

__global__ __launch_bounds__(128, 2)
void gemm_kv_f16(const __half* __restrict__ A, const __half* __restrict__ Bt,
                 float* __restrict__ K, float* __restrict__ V,
                 const float* __restrict__ cf, const float* __restrict__ sf,
                 const float* __restrict__ rel_table,
                 const int* __restrict__ memidx, const int* __restrict__ cur,
                 int M)
{
    __shared__ __half As[2][128 * HSTR];
    __shared__ __half Bs[2][128 * HSTR];

    const int tid  = threadIdx.x;
    const int wid  = tid >> 5, lane = tid & 31;
    const int g    = lane >> 2, tg = lane & 3;
    const int wm   = (wid >> 1) * 64;
    const int wn   = (wid & 1) * 64;
    const int m0   = blockIdx.y * 128, n0 = blockIdx.x * 128;

    float d[4][8][4];
#pragma unroll
    for (int i = 0; i < 4; i++)
#pragma unroll
        for (int j = 0; j < 8; j++)
#pragma unroll
            for (int q = 0; q < 4; q++) d[i][j][q] = 0.f;

    auto issue = [&](int buf, int kt) {
        const int k0 = kt * 32;
#pragma unroll
        for (int e = 0; e < 4; e++) {
            int idx = tid + e * 128;        // 0..511
            int row = idx >> 2, c8 = (idx & 3) * 8;   // 8-half (16B) chunk
            int ga = m0 + row;
            int pa = (ga < M) ? 16 : 0;
            if (ga >= M) ga = M - 1;
            uint32_t da = smem_u32(&As[buf][row * HSTR + c8]);
            CP16P(da, A + (size_t)ga * 1024u + k0 + c8, pa);
            uint32_t db = smem_u32(&Bs[buf][row * HSTR + c8]);
            CP16(db, Bt + (size_t)(n0 + row) * 1024u + k0 + c8);
        }
        CP_COMMIT();
    };

    issue(0, 0);
    issue(1, 1);

    for (int kt = 0; kt < 32; kt++) {
        const int buf = kt & 1;
        if (kt < 31) CP_WAIT(1);
        else         CP_WAIT(0);
        __syncthreads();

#pragma unroll
        for (int ks = 0; ks < 2; ks++) {     // two k16 steps per BK=32
            uint32_t af[4][4], bf[8][2];
#pragma unroll
            for (int i = 0; i < 4; i++) {
                const __half* base = &As[buf][(wm + i * 16) * HSTR + ks * 16];
                af[i][0] = *(const uint32_t*)&base[(g)     * HSTR + 2 * tg];
                af[i][1] = *(const uint32_t*)&base[(g + 8) * HSTR + 2 * tg];
                af[i][2] = *(const uint32_t*)&base[(g)     * HSTR + 2 * tg + 8];
                af[i][3] = *(const uint32_t*)&base[(g + 8) * HSTR + 2 * tg + 8];
            }
#pragma unroll
            for (int j = 0; j < 8; j++) {
                const __half* base = &Bs[buf][(wn + j * 8 + g) * HSTR + ks * 16];
                bf[j][0] = *(const uint32_t*)&base[2 * tg];
                bf[j][1] = *(const uint32_t*)&base[2 * tg + 8];
            }
#pragma unroll
            for (int i = 0; i < 4; i++)
#pragma unroll
                for (int j = 0; j < 8; j++)
                    MMA_F16(d[i][j][0], d[i][j][1], d[i][j][2], d[i][j][3],
                            af[i][0], af[i][1], af[i][2], af[i][3],
                            bf[j][0], bf[j][1]);
        }
        __syncthreads();
        if (kt + 2 < 32) issue(buf, kt + 2);
    }

    // ---------------- epilogue ---------------------------------------------
    const bool kblk = (n0 < 1024);
    float* Co = kblk ? K : V;
    const int cb = kblk ? n0 : (n0 - 1024);

    const int cp = cur[0];
    const int ci = cp % 16;
    const int rs = ci % 4, cs = ci / 4, ts = cp / 16;
    const int hwarp = (n0 + wn) >> 6;

#pragma unroll
    for (int i = 0; i < 4; i++) {
        const int rA = m0 + wm + i * 16 + g;
        const int rB = rA + 8;

        float biasA = 0.f, biasB = 0.f;
        int fobA = 0, fobB = 0;
        bool tA = false, tB = false;
        if (kblk) {
            {
                const int b_ = rA / KVn, j = rA - b_ * KVn;
                if (j < MSn) {
                    const int m = j >> 8, jj = j & 255;
                    const int mi = memidx[m], mn = mi % 16;
                    const int rt = mn % 4, ct = mn / 4, tt = mi / 16;
                    const int rel = (rt - rs + 4) * 9 + (ct - cs + 4) + (tt - ts + 4) * 81;
                    biasA = rel_table[rel * HEADSn + hwarp];
                    fobA = (((rt * 16 + (jj >> 4)) << 6) + (ct * 16 + (jj & 15))) * 64;
                    tA = true;
                }
            }
            {
                const int b_ = rB / KVn, j = rB - b_ * KVn;
                if (j < MSn) {
                    const int m = j >> 8, jj = j & 255;
                    const int mi = memidx[m], mn = mi % 16;
                    const int rt = mn % 4, ct = mn / 4, tt = mi / 16;
                    const int rel = (rt - rs + 4) * 9 + (ct - cs + 4) + (tt - ts + 4) * 81;
                    biasB = rel_table[rel * HEADSn + hwarp];
                    fobB = (((rt * 16 + (jj >> 4)) << 6) + (ct * 16 + (jj & 15))) * 64;
                    tB = true;
                }
            }
        }

#pragma unroll
        for (int j = 0; j < 8; j++) {
            const int c  = cb + wn + j * 8 + tg * 2;
            const int d0 = (wn + j * 8 + tg * 2) & 63;
            float2 v0 = make_float2(d[i][j][0], d[i][j][1]);
            float2 v1 = make_float2(d[i][j][2], d[i][j][3]);
            if (kblk) {
                if (tA) rot_pair(v0, biasA, cf, sf, fobA + d0);
                if (tB) rot_pair(v1, biasB, cf, sf, fobB + d0);
            } else {
                v0.x = rna_tf32(v0.x); v0.y = rna_tf32(v0.y);
                v1.x = rna_tf32(v1.x); v1.y = rna_tf32(v1.y);
            }
            if (rA < M) *(float2*)&Co[(size_t)rA * 1024u + c] = v0;
            if (rB < M) *(float2*)&Co[(size_t)rB * 1024u + c] = v1;
        }
    }
}

// =================== tf32 mma GEMM (Q and out projections) =================
#define SA_STR 20

template<bool BIAS, bool QPOST>
__global__ __launch_bounds__(128, 2)
void gemm_mma(const float* __restrict__ A, const float* __restrict__ Bt,
              float* __restrict__ C, const float* __restrict__ bias,
              const float* __restrict__ cf, const float* __restrict__ sf,
              const int* __restrict__ cur, int M)
{
    __shared__ float As[2][128 * SA_STR];
    __shared__ float Bs[2][128 * SA_STR];

    const int tid  = threadIdx.x;
    const int wid  = tid >> 5, lane = tid & 31;
    const int g    = lane >> 2, tg = lane & 3;
    const int wm   = (wid >> 1) * 64;
    const int wn   = (wid & 1) * 64;
    const int m0   = blockIdx.y * 128, n0 = blockIdx.x * 128;

    float d[4][8][4];
#pragma unroll
    for (int i = 0; i < 4; i++)
#pragma unroll
        for (int j = 0; j < 8; j++)
#pragma unroll
            for (int q = 0; q < 4; q++) d[i][j][q] = 0.f;

    auto issue = [&](int buf, int kt) {
        const int k0 = kt * 16;
#pragma unroll
        for (int e = 0; e < 4; e++) {
            int idx = tid + e * 128;
            int row = idx >> 2, c4 = idx & 3;
            int ga = m0 + row;
            int pa = (ga < M) ? 16 : 0;
            if (ga >= M) ga = M - 1;
            uint32_t da = smem_u32(&As[buf][row * SA_STR + c4 * 4]);
            CP16P(da, A + (size_t)ga * 1024u + k0 + c4 * 4, pa);
            uint32_t db = smem_u32(&Bs[buf][row * SA_STR + c4 * 4]);
            CP16(db, Bt + (size_t)(n0 + row) * 1024u + k0 + c4 * 4);
        }
        CP_COMMIT();
    };

    issue(0, 0);
    issue(1, 1);

    for (int kt = 0; kt < 64; kt++) {
        const int buf = kt & 1;
        if (kt < 63) CP_WAIT(1);
        else         CP_WAIT(0);
        __syncthreads();

#pragma unroll
        for (int ks = 0; ks < 2; ks++) {
            uint32_t af[4][4], bf[8][2];
#pragma unroll
            for (int i = 0; i < 4; i++) {
                const float* base = &As[buf][(wm + i * 16) * SA_STR + ks * 8];
                af[i][0] = __float_as_uint(base[(g)     * SA_STR + tg]);
                af[i][1] = __float_as_uint(base[(g + 8) * SA_STR + tg]);
                af[i][2] = __float_as_uint(base[(g)     * SA_STR + tg + 4]);
                af[i][3] = __float_as_uint(base[(g + 8) * SA_STR + tg + 4]);
            }
#pragma unroll
            for (int j = 0; j < 8; j++) {
                const float* base = &Bs[buf][(wn + j * 8 + g) * SA_STR + ks * 8];
                bf[j][0] = __float_as_uint(base[tg]);
                bf[j][1] = __float_as_uint(base[tg + 4]);
            }
#pragma unroll
            for (int i = 0; i < 4; i++)
#pragma unroll
                for (int j = 0; j < 8; j++)
                    MMA_TF32(d[i][j][0], d[i][j][1], d[i][j][2], d[i][j][3],
                             af[i][0], af[i][1], af[i][2], af[i][3],
                             bf[j][0], bf[j][1]);
        }
        __syncthreads();
        if (kt + 2 < 64) issue(buf, kt + 2);
    }

    int rs = 0, cs = 0;
    if (QPOST) {
        const int ci = cur[0] % 16;
        rs = ci % 4; cs = ci / 4;
    }

#pragma unroll
    for (int i = 0; i < 4; i++) {
        const int rA = m0 + wm + i * 16 + g;
        const int rB = rA + 8;
        int fobA = 0, fobB = 0;
        if (QPOST) {
            { const int s = rA & 255;
              fobA = (((rs * 16 + (s >> 4)) << 6) + (cs * 16 + (s & 15))) * 64; }
            { const int s = rB & 255;
              fobB = (((rs * 16 + (s >> 4)) << 6) + (cs * 16 + (s & 15))) * 64; }
        }
#pragma unroll
        for (int j = 0; j < 8; j++) {
            const int c  = n0 + wn + j * 8 + tg * 2;
            const int d0 = (wn + j * 8 + tg * 2) & 63;
            float2 v0 = make_float2(d[i][j][0], d[i][j][1]);
            float2 v1 = make_float2(d[i][j][2], d[i][j][3]);
            if (BIAS) {
                const float b0 = bias[c], b1 = bias[c + 1];
                v0.x += b0; v0.y += b1; v1.x += b0; v1.y += b1;
            }
            if (QPOST) {
                rot_pair(v0, 0.f, cf, sf, fobA + d0);
                rot_pair(v1, 0.f, cf, sf, fobB + d0);
                v0.x = rna_tf32(v0.x * SCALEf); v0.y = rna_tf32(v0.y * SCALEf);
                v1.x = rna_tf32(v1.x * SCALEf); v1.y = rna_tf32(v1.y * SCALEf);
            }
            if (rA < M) *(float2*)&C[(size_t)rA * 1024u + c] = v0;
            if (rB < M) *(float2*)&C[(size_t)rB * 1024u + c] = v1;
        }
    }
}

// =================== fused flash attention (tf32 mma) ======================
#define QS_O 0
#define KS_O (QS_O + 128*68)
#define VS_O (KS_O + 64*68)
#define SS_O (VS_O + 64*72)
#define MR_O (SS_O + 128*68)
#define LR_O (MR_O + 128)
#define AR_O (LR_O + 128)
#define FL_SMEM ((AR_O + 128) * 4)

#define NCHUNK ((KVn + 63) / 64)

__global__ __launch_bounds__(256, 2)
void flash_attn(const float* __restrict__ Q, const float* __restrict__ K,
                const float* __restrict__ V, float* __restrict__ O)
{
    extern __shared__ float sm[];
    const int tid = threadIdx.x;
    const int wid = tid >> 5, lane = tid & 31;
    const int g = lane >> 2, tg = lane & 3;
    const int bh = blockIdx.y, b = bh >> 4, h = bh & 15;
    const int m0 = blockIdx.x * 128;

    const float* Qb = Q + ((size_t)(b * SEQn + m0)) * 1024u + h * 64;
    const float* Kb = K + ((size_t)b * KVn) * 1024u + h * 64;
    const float* Vb = V + ((size_t)b * KVn) * 1024u + h * 64;

    for (int e = tid; e < 128 * 64; e += 256) {
        int r = e >> 6, c = e & 63;
        sm[QS_O + r * 68 + c] = Qb[(size_t)r * 1024u + c];
    }
    if (tid < 128) { sm[MR_O + tid] = -1e30f; sm[LR_O + tid] = 0.f; }

    float oacc[4][2][4];
#pragma unroll
    for (int i = 0; i < 4; i++)
#pragma unroll
        for (int j = 0; j < 2; j++)
#pragma unroll
            for (int q = 0; q < 4; q++) oacc[i][j][q] = 0.f;

    const int om = (wid >> 2) * 64;
    const int on = (wid & 3) * 16;
    __syncthreads();

    for (int t = 0; t < NCHUNK; t++) {
        const int kv0 = t * 64;
        const int rows = (KVn - kv0 < 64) ? (KVn - kv0) : 64;

#pragma unroll
        for (int e = 0; e < 4; e++) {
            int idx = tid + e * 256;
            int r = idx >> 4, c4 = idx & 15;
            int kvr = kv0 + r; if (kvr >= KVn) kvr = KVn - 1;
            uint32_t dk = smem_u32(&sm[KS_O + r * 68 + c4 * 4]);
            CP16(dk, Kb + (size_t)kvr * 1024u + c4 * 4);
            uint32_t dv = smem_u32(&sm[VS_O + r * 72 + c4 * 4]);
            CP16(dv, Vb + (size_t)kvr * 1024u + c4 * 4);
        }
        CP_COMMIT();
        CP_WAIT(0);
        __syncthreads();

        float s[4][2][4];
#pragma unroll
        for (int i = 0; i < 4; i++)
#pragma unroll
            for (int j = 0; j < 2; j++)
#pragma unroll
                for (int q = 0; q < 4; q++) s[i][j][q] = 0.f;

#pragma unroll
        for (int ks = 0; ks < 8; ks++) {
            uint32_t af[4][4], bf[2][2];
#pragma unroll
            for (int i = 0; i < 4; i++) {
                const float* base = &sm[QS_O + (om + i * 16) * 68 + ks * 8];
                af[i][0] = __float_as_uint(base[(g)     * 68 + tg]);
                af[i][1] = __float_as_uint(base[(g + 8) * 68 + tg]);
                af[i][2] = __float_as_uint(base[(g)     * 68 + tg + 4]);
                af[i][3] = __float_as_uint(base[(g + 8) * 68 + tg + 4]);
            }
#pragma unroll
            for (int j = 0; j < 2; j++) {
                const float* base = &sm[KS_O + (on + j * 8 + g) * 68 + ks * 8];
                bf[j][0] = __float_as_uint(base[tg]);
                bf[j][1] = __float_as_uint(base[tg + 4]);
            }
#pragma unroll
            for (int i = 0; i < 4; i++)
#pragma unroll
                for (int j = 0; j < 2; j++)
                    MMA_TF32(s[i][j][0], s[i][j][1], s[i][j][2], s[i][j][3],
                             af[i][0], af[i][1], af[i][2], af[i][3],
                             bf[j][0], bf[j][1]);
        }
#pragma unroll
        for (int i = 0; i < 4; i++) {
            const int r0 = om + i * 16 + g;
#pragma unroll
            for (int j = 0; j < 2; j++) {
                const int c = on + j * 8 + tg * 2;
                sm[SS_O + r0 * 68 + c]           = s[i][j][0];
                sm[SS_O + r0 * 68 + c + 1]       = s[i][j][1];
                sm[SS_O + (r0 + 8) * 68 + c]     = s[i][j][2];
                sm[SS_O + (r0 + 8) * 68 + c + 1] = s[i][j][3];
            }
        }
        __syncthreads();

#pragma unroll 4
        for (int rr = 0; rr < 16; rr++) {
            const int r = wid * 16 + rr;
            const int c0 = lane * 2;
            float v0 = (c0     < rows) ? sm[SS_O + r * 68 + c0]     : -1e30f;
            float v1 = (c0 + 1 < rows) ? sm[SS_O + r * 68 + c0 + 1] : -1e30f;
            float mx = fmaxf(v0, v1);
#pragma unroll
            for (int o = 16; o; o >>= 1) mx = fmaxf(mx, __shfl_xor_sync(~0u, mx, o));
            const float mold = sm[MR_O + r];
            const float mnew = fmaxf(mold, mx);
            float p0 = (c0     < rows) ? rna_tf32(__expf(v0 - mnew)) : 0.f;
            float p1 = (c0 + 1 < rows) ? rna_tf32(__expf(v1 - mnew)) : 0.f;
            sm[SS_O + r * 68 + c0]     = p0;
            sm[SS_O + r * 68 + c0 + 1] = p1;
            float ls = p0 + p1;
#pragma unroll
            for (int o = 16; o; o >>= 1) ls += __shfl_xor_sync(~0u, ls, o);
            if (lane == 0) {
                const float al = __expf(mold - mnew);
                sm[AR_O + r] = al;
                sm[LR_O + r] = sm[LR_O + r] * al + ls;
                sm[MR_O + r] = mnew;
            }
        }
        __syncthreads();

#pragma unroll
        for (int i = 0; i < 4; i++) {
            const float a0 = sm[AR_O + om + i * 16 + g];
            const float a1 = sm[AR_O + om + i * 16 + g + 8];
#pragma unroll
            for (int j = 0; j < 2; j++) {
                oacc[i][j][0] *= a0; oacc[i][j][1] *= a0;
                oacc[i][j][2] *= a1; oacc[i][j][3] *= a1;
            }
        }

#pragma unroll
        for (int ks = 0; ks < 8; ks++) {
            uint32_t af[4][4], bf[2][2];
#pragma unroll
            for (int i = 0; i < 4; i++) {
                const float* base = &sm[SS_O + (om + i * 16) * 68 + ks * 8];
                af[i][0] = __float_as_uint(base[(g)     * 68 + tg]);
                af[i][1] = __float_as_uint(base[(g + 8) * 68 + tg]);
                af[i][2] = __float_as_uint(base[(g)     * 68 + tg + 4]);
                af[i][3] = __float_as_uint(base[(g + 8) * 68 + tg + 4]);
            }
#pragma unroll
            for (int j = 0; j < 2; j++) {
                bf[j][0] = __float_as_uint(sm[VS_O + (ks * 8 + tg)     * 72 + on + j * 8 + g]);
                bf[j][1] = __float_as_uint(sm[VS_O + (ks * 8 + tg + 4) * 72 + on + j * 8 + g]);
            }
#pragma unroll
            for (int i = 0; i < 4; i++)
#pragma unroll
                for (int j = 0; j < 2; j++)
                    MMA_TF32(oacc[i][j][0], oacc[i][j][1], oacc[i][j][2], oacc[i][j][3],
                             af[i][0], af[i][1], af[i][2], af[i][3],
                             bf[j][0], bf[j][1]);
        }
        __syncthreads();
    }

    float* Ob = O + ((size_t)(b * SEQn + m0)) * 1024u + h * 64;
#pragma unroll
    for (int i = 0; i < 4; i++) {
        const int r0 = om + i * 16 + g;
        const float li0 = 1.f / sm[LR_O + r0];
        const float li1 = 1.f / sm[LR_O + r0 + 8];
#pragma unroll
        for (int j = 0; j < 2; j++) {
            const int c = on + j * 8 + tg * 2;
            float2 v0 = make_float2(rna_tf32(oacc[i][j][0] * li0), rna_tf32(oacc[i][j][1] * li0));
            float2 v1 = make_float2(rna_tf32(oacc[i][j][2] * li1), rna_tf32(oacc[i][j][3] * li1));
            *(float2*)&Ob[(size_t)r0 * 1024u + c]       = v0;
            *(float2*)&Ob[(size_t)(r0 + 8) * 1024u + c] = v1;
        }
    }
}

// ---------------- weight transpose (fp32 rna / fp16 rn) --------------------
__global__ void transpose_1024(const float* __restrict__ W, float* __restrict__ Wt)
{
    __shared__ float t[32][33];
    const int bx = blockIdx.x * 32, by = blockIdx.y * 32;
    const int tx = threadIdx.x, ty = threadIdx.y;
#pragma unroll
    for (int i = 0; i < 4; i++)
        t[ty + i * 8][tx] = W[(size_t)(by + ty + i * 8) * 1024 + bx + tx];
    __syncthreads();
#pragma unroll
    for (int i = 0; i < 4; i++)
        Wt[(size_t)(bx + ty + i * 8) * 1024 + by + tx] = rna_tf32(t[tx][ty + i * 8]);
}

__global__ void transpose_1024_h(const float* __restrict__ W, __half* __restrict__ Wt)
{
    __shared__ float t[32][33];
    const int bx = blockIdx.x * 32, by = blockIdx.y * 32;
    const int tx = threadIdx.x, ty = threadIdx.y;
#pragma unroll
    for (int i = 0; i < 4; i++)
        t[ty + i * 8][tx] = W[(size_t)(by + ty + i * 8) * 1024 + bx + tx];
    __syncthreads();
#pragma unroll
    for (int i = 0; i < 4; i++)
        Wt[(size_t)(bx + ty + i * 8) * 1024 + by + tx] = __float2half_rn(t[tx][ty + i * 8]);
}

// ---------------- rounding / conversion copies -----------------------------
__global__ void round_copy(const float4* __restrict__ in, float4* __restrict__ out, int n4)
{
    int i = blockIdx.x * blockDim.x + threadIdx.x;
    if (i < n4) {
        float4 v = in[i];
        v.x = rna_tf32(v.x); v.y = rna_tf32(v.y);
        v.z = rna_tf32(v.z); v.w = rna_tf32(v.w);
        out[i] = v;
    }
}

__global__ void half_copy(const float4* __restrict__ in, __half2* __restrict__ out, int n4)
{
    int i = blockIdx.x * blockDim.x + threadIdx.x;
    if (i < n4) {
        float4 v = in[i];
        out[2 * i]     = __floats2half2_rn(v.x, v.y);
        out[2 * i + 1] = __floats2half2_rn(v.z, v.w);
    }
}

__global__ void cs_precompute(const float* __restrict__ freqs,
                              float* __restrict__ cf, float* __restrict__ sf)
{
    int i = blockIdx.x * blockDim.x + threadIdx.x;
    if (i < 64*64*64) {
        float v = freqs[i];
        cf[i] = cosf(v);
        sf[i] = sinf(v);
    }
}

// ---------------- host launch ----------------------------------------------
extern "C" void kernel_launch(void* const* d_in, const int* in_sizes, int n_in,
                              void* d_out, int out_size)
{
    const float* x     = (const float*)d_in[0];
    const float* cond  = (const float*)d_in[1];
    const float* freqs = (const float*)d_in[2];
    const float* Wq    = (const float*)d_in[3];
    const float* Wk    = (const float*)d_in[4];
    const float* Wv    = (const float*)d_in[5];
    const float* rel   = (const float*)d_in[6];
    const float* Wo    = (const float*)d_in[7];
    const float* bo    = (const float*)d_in[8];
    const int*   memi  = (const int*)d_in[9];
    const int*   cur   = (const int*)d_in[10];
    float* out = (float*)d_out;

    float *Qb, *Kb, *Vb, *Ob, *Wt, *Xr, *Cf, *Sf;
    __half *Whkv, *Ch;
    cudaGetSymbolAddress((void**)&Qb, g_Q);
    cudaGetSymbolAddress((void**)&Kb, g_K);
    cudaGetSymbolAddress((void**)&Vb, g_V);
    cudaGetSymbolAddress((void**)&Ob, g_O);
    cudaGetSymbolAddress((void**)&Wt, g_Wt);
    cudaGetSymbolAddress((void**)&Xr, g_Xr);
    cudaGetSymbolAddress((void**)&Cf, g_cosf);
    cudaGetSymbolAddress((void**)&Sf, g_sinf);
    cudaGetSymbolAddress((void**)&Whkv, g_Whkv);
    cudaGetSymbolAddress((void**)&Ch, g_Ch);

    cudaFuncSetAttribute(flash_attn, cudaFuncAttributeMaxDynamicSharedMemorySize, FL_SMEM);

    float* Wtq = Wt;
    float* Wto = Wt + (size_t)DIMn * INNERn;

    // prep
    half_copy<<<(ROWS_C*DIMn/4 + 255)/256, 256>>>((const float4*)cond, (__half2*)Ch, ROWS_C*DIMn/4);
    round_copy<<<(ROWS_X*DIMn/4 + 255)/256, 256>>>((const float4*)x, (float4*)Xr, ROWS_X*DIMn/4);
    cs_precompute<<<(64*64*64 + 255)/256, 256>>>(freqs, Cf, Sf);
    transpose_1024_h<<<dim3(32,32), dim3(32,8)>>>(Wk, Whkv);
    transpose_1024_h<<<dim3(32,32), dim3(32,8)>>>(Wv, Whkv + (size_t)DIMn * INNERn);
    transpose_1024<<<dim3(32,32), dim3(32,8)>>>(Wq, Wtq);
    transpose_1024<<<dim3(32,32), dim3(32,8)>>>(Wo, Wto);

    // merged K|V projection on fp16 tensor cores (K: bias+rotary; V: rna)
    gemm_kv_f16<<<dim3(16, 266), 128>>>(Ch, Whkv, Kb, Vb, Cf, Sf, rel, memi, cur, ROWS_C);

    // Q projection (tf32); fused rotary + scale + rna
    gemm_mma<false,true><<<dim3(8, 32), 128>>>(Xr, Wtq, Qb, nullptr, Cf, Sf, cur, ROWS_X);

    // fused flash attention
    flash_attn<<<dim3(2, BHn), 256, FL_SMEM>>>(Qb, Kb, Vb, Ob);

    // out = O @ Wo + bo (tf32)
    gemm_mma<true,false><<<dim3(8, 32), 128>>>(Ob, Wto, out, bo, nullptr, nullptr, nullptr, ROWS_X);
}

// round 14
// speedup vs baseline: 1.5250x; 1.1285x over previous
#include <cuda_runtime.h>
#include <cuda_fp16.h>
#include <cstdint>
#include <cstddef>

// ---------------- problem constants (fixed by the dataset) ----------------
#define Bn     16
#define SEQn   256
#define DIMn   1024
#define HEADSn 16
#define DHEADn 64
#define INNERn 1024
#define Mmem   8
#define TXTn   77
#define KVn    (Mmem*SEQn + TXTn)   // 2125
#define KVP    2176                 // padded kv for transposed V
#define MSn    (Mmem*SEQn)          // 2048
#define SCALEf 0.125f               // 64^-0.5

#define ROWS_X   (Bn*SEQn)          // 4096
#define ROWS_C   (Bn*KVn)           // 34000
#define BHn      (Bn*HEADSn)        // 256

// ---------------- scratch (device globals: no allocation allowed) ---------
__device__ __half g_Qh[ROWS_X * INNERn];        // rotated+scaled Q (half)
__device__ __half g_Kh[ROWS_C * INNERn];        // biased+rotated K (half)
__device__ __half g_Vt[(size_t)BHn * 64 * KVP]; // V transposed per (b,h): [d][kv]
__device__ float  g_O[ROWS_X * INNERn];
__device__ float  g_Wt[2 * DIMn * INNERn];      // Wtq, Wto (tf32)
__device__ __half g_Whkv[2 * DIMn * INNERn];    // [Wtk;Wtv] K-major halves
__device__ __half g_Ch[ROWS_C * DIMn];          // half(cond)
__device__ float  g_Xr[ROWS_X * DIMn];          // rna(x)
__device__ float  g_cosf[64*64*64];
__device__ float  g_sinf[64*64*64];

// ---------------- helpers --------------------------------------------------
__device__ __forceinline__ uint32_t smem_u32(const void* p) {
    uint32_t a;
    asm("{ .reg .u64 t; cvta.to.shared.u64 t, %1; cvt.u32.u64 %0, t; }" : "=r"(a) : "l"(p));
    return a;
}
__device__ __forceinline__ float rna_tf32(float x) {
    float y;
    asm("cvt.rna.tf32.f32 %0, %1;" : "=f"(y) : "f"(x));
    return y;
}
__device__ __forceinline__ void rot_pair(float2& v, float bias,
                                         const float* __restrict__ cf,
                                         const float* __restrict__ sf, int fo) {
    const float t0 = v.x + bias, t1 = v.y + bias;
    v.x = t0 * cf[fo]     - t1 * sf[fo];
    v.y = t1 * cf[fo + 1] + t0 * sf[fo + 1];
}
#define MMA_TF32(d0,d1,d2,d3,a0,a1,a2,a3,b0,b1)                               \
    asm volatile(                                                             \
        "mma.sync.aligned.m16n8k8.row.col.f32.tf32.tf32.f32 "                 \
        "{%0,%1,%2,%3},{%4,%5,%6,%7},{%8,%9},{%0,%1,%2,%3};"                  \
        : "+f"(d0), "+f"(d1), "+f"(d2), "+f"(d3)                              \
        : "r"(a0), "r"(a1), "r"(a2), "r"(a3), "r"(b0), "r"(b1))
#define MMA_F16(d0,d1,d2,d3,a0,a1,a2,a3,b0,b1)                                \
    asm volatile(                                                             \
        "mma.sync.aligned.m16n8k16.row.col.f32.f16.f16.f32 "                  \
        "{%0,%1,%2,%3},{%4,%5,%6,%7},{%8,%9},{%0,%1,%2,%3};"                  \
        : "+f"(d0), "+f"(d1), "+f"(d2), "+f"(d3)                              \
        : "r"(a0), "r"(a1), "r"(a2), "r"(a3), "r"(b0), "r"(b1))
#define CP16(dst, src)     asm volatile("cp.async.cg.shared.global [%0], [%1], 16;" :: "r"(dst), "l"(src))
#define CP16P(dst, src, p) asm volatile("cp.async.cg.shared.global [%0], [%1], 16, %2;" :: "r"(dst), "l"(src), "r"(p))
#define CP_COMMIT()        asm volatile("cp.async.commit_group;" ::: "memory")
#define CP_WAIT(n)         asm volatile("cp.async.wait_group %0;" :: "n"(n) : "memory")

// =================== fp16 mma GEMM: merged K|V projection ==================
// K half: epilogue rel-bias + rotary on mem rows -> g_Kh (half).
// V half: epilogue writes transposed halves -> g_Vt[(b,h,d)][kv].
#define HSTR 40

__global__ __launch_bounds__(128, 2)
void gemm_kv_f16(const __half* __restrict__ A, const __half* __restrict__ Bt,
                 __half* __restrict__ Kh, __half* __restrict__ Vt,
                 const float* __restrict__ cf, const float* __restrict__ sf,
                 const float* __restrict__ rel_table,
                 const int* __restrict__ memidx, const int* __restrict__ cur,
                 int M)
{
    __shared__ __half As[2][128 * HSTR];
    __shared__ __half Bs[2][128 * HSTR];

    const int tid  = threadIdx.x;
    const int wid  = tid >> 5, lane = tid & 31;
    const int g    = lane >> 2, tg = lane & 3;
    const int wm   = (wid >> 1) * 64;
    const int wn   = (wid & 1) * 64;
    const int m0   = blockIdx.y * 128, n0 = blockIdx.x * 128;

    float d[4][8][4];
#pragma unroll
    for (int i = 0; i < 4; i++)
#pragma unroll
        for (int j = 0; j < 8; j++)
#pragma unroll
            for (int q = 0; q < 4; q++) d[i][j][q] = 0.f;

    auto issue = [&](int buf, int kt) {
        const int k0 = kt * 32;
#pragma unroll
        for (int e = 0; e < 4; e++) {
            int idx = tid + e * 128;
            int row = idx >> 2, c8 = (idx & 3) * 8;
            int ga = m0 + row;
            int pa = (ga < M) ? 16 : 0;
            if (ga >= M) ga = M - 1;
            uint32_t da = smem_u32(&As[buf][row * HSTR + c8]);
            CP16P(da, A + (size_t)ga * 1024u + k0 + c8, pa);
            uint32_t db = smem_u32(&Bs[buf][row * HSTR + c8]);
            CP16(db, Bt + (size_t)(n0 + row) * 1024u + k0 + c8);
        }
        CP_COMMIT();
    };

    issue(0, 0);
    issue(1, 1);

    for (int kt = 0; kt < 32; kt++) {
        const int buf = kt & 1;
        if (kt < 31) CP_WAIT(1);
        else         CP_WAIT(0);
        __syncthreads();

#pragma unroll
        for (int ks = 0; ks < 2; ks++) {
            uint32_t af[4][4], bf[8][2];
#pragma unroll
            for (int i = 0; i < 4; i++) {
                const __half* base = &As[buf][(wm + i * 16) * HSTR + ks * 16];
                af[i][0] = *(const uint32_t*)&base[(g)     * HSTR + 2 * tg];
                af[i][1] = *(const uint32_t*)&base[(g + 8) * HSTR + 2 * tg];
                af[i][2] = *(const uint32_t*)&base[(g)     * HSTR + 2 * tg + 8];
                af[i][3] = *(const uint32_t*)&base[(g + 8) * HSTR + 2 * tg + 8];
            }
#pragma unroll
            for (int j = 0; j < 8; j++) {
                const __half* base = &Bs[buf][(wn + j * 8 + g) * HSTR + ks * 16];
                bf[j][0] = *(const uint32_t*)&base[2 * tg];
                bf[j][1] = *(const uint32_t*)&base[2 * tg + 8];
            }
#pragma unroll
            for (int i = 0; i < 4; i++)
#pragma unroll
                for (int j = 0; j < 8; j++)
                    MMA_F16(d[i][j][0], d[i][j][1], d[i][j][2], d[i][j][3],
                            af[i][0], af[i][1], af[i][2], af[i][3],
                            bf[j][0], bf[j][1]);
        }
        __syncthreads();
        if (kt + 2 < 32) issue(buf, kt + 2);
    }

    // ---------------- epilogue ---------------------------------------------
    const bool kblk = (n0 < 1024);
    const int cb = kblk ? n0 : (n0 - 1024);

    const int cp = cur[0];
    const int ci = cp % 16;
    const int rs = ci % 4, cs = ci / 4, ts = cp / 16;
    const int hwarp = (n0 + wn) >> 6;   // K-block head (warp-uniform there)

#pragma unroll
    for (int i = 0; i < 4; i++) {
        const int rA = m0 + wm + i * 16 + g;
        const int rB = rA + 8;

        float biasA = 0.f, biasB = 0.f;
        int fobA = 0, fobB = 0;
        bool tA = false, tB = false;
        if (kblk) {
            {
                const int b_ = rA / KVn, j = rA - b_ * KVn;
                if (j < MSn) {
                    const int m = j >> 8, jj = j & 255;
                    const int mi = memidx[m], mn = mi % 16;
                    const int rt = mn % 4, ct = mn / 4, tt = mi / 16;
                    const int rel = (rt - rs + 4) * 9 + (ct - cs + 4) + (tt - ts + 4) * 81;
                    biasA = rel_table[rel * HEADSn + hwarp];
                    fobA = (((rt * 16 + (jj >> 4)) << 6) + (ct * 16 + (jj & 15))) * 64;
                    tA = true;
                }
            }
            {
                const int b_ = rB / KVn, j = rB - b_ * KVn;
                if (j < MSn) {
                    const int m = j >> 8, jj = j & 255;
                    const int mi = memidx[m], mn = mi % 16;
                    const int rt = mn % 4, ct = mn / 4, tt = mi / 16;
                    const int rel = (rt - rs + 4) * 9 + (ct - cs + 4) + (tt - ts + 4) * 81;
                    biasB = rel_table[rel * HEADSn + hwarp];
                    fobB = (((rt * 16 + (jj >> 4)) << 6) + (ct * 16 + (jj & 15))) * 64;
                    tB = true;
                }
            }
        }

#pragma unroll
        for (int j = 0; j < 8; j++) {
            const int c  = cb + wn + j * 8 + tg * 2;
            const int d0 = (wn + j * 8 + tg * 2) & 63;
            float2 v0 = make_float2(d[i][j][0], d[i][j][1]);
            float2 v1 = make_float2(d[i][j][2], d[i][j][3]);
            if (kblk) {
                if (tA) rot_pair(v0, biasA, cf, sf, fobA + d0);
                if (tB) rot_pair(v1, biasB, cf, sf, fobB + d0);
                if (rA < M) *(__half2*)&Kh[(size_t)rA * 1024u + c] = __floats2half2_rn(v0.x, v0.y);
                if (rB < M) *(__half2*)&Kh[(size_t)rB * 1024u + c] = __floats2half2_rn(v1.x, v1.y);
            } else {
                // V: write transposed halves Vt[(b,h,d)][kv]
                const int hh = c >> 6, dd = c & 63;
                if (rA < M) {
                    const int b_ = rA / KVn, jv = rA - b_ * KVn;
                    __half* vt = Vt + ((size_t)(b_ * HEADSn + hh) * 64) * KVP + jv;
                    vt[(size_t)dd * KVP]       = __float2half_rn(v0.x);
                    vt[(size_t)(dd + 1) * KVP] = __float2half_rn(v0.y);
                }
                if (rB < M) {
                    const int b_ = rB / KVn, jv = rB - b_ * KVn;
                    __half* vt = Vt + ((size_t)(b_ * HEADSn + hh) * 64) * KVP + jv;
                    vt[(size_t)dd * KVP]       = __float2half_rn(v1.x);
                    vt[(size_t)(dd + 1) * KVP] = __float2half_rn(v1.y);
                }
            }
        }
    }
}

// =================== tf32 mma GEMM (Q and out projections) =================
#define SA_STR 20

template<bool BIAS, bool QPOST>
__global__ __launch_bounds__(128, 2)
void gemm_mma(const float* __restrict__ A, const float* __restrict__ Bt,
              float* __restrict__ C, __half* __restrict__ Ch,
              const float* __restrict__ bias,
              const float* __restrict__ cf, const float* __restrict__ sf,
              const int* __restrict__ cur, int M)
{
    __shared__ float As[2][128 * SA_STR];
    __shared__ float Bs[2][128 * SA_STR];

    const int tid  = threadIdx.x;
    const int wid  = tid >> 5, lane = tid & 31;
    const int g    = lane >> 2, tg = lane & 3;
    const int wm   = (wid >> 1) * 64;
    const int wn   = (wid & 1) * 64;
    const int m0   = blockIdx.y * 128, n0 = blockIdx.x * 128;

    float d[4][8][4];
#pragma unroll
    for (int i = 0; i < 4; i++)
#pragma unroll
        for (int j = 0; j < 8; j++)
#pragma unroll
            for (int q = 0; q < 4; q++) d[i][j][q] = 0.f;

    auto issue = [&](int buf, int kt) {
        const int k0 = kt * 16;
#pragma unroll
        for (int e = 0; e < 4; e++) {
            int idx = tid + e * 128;
            int row = idx >> 2, c4 = idx & 3;
            int ga = m0 + row;
            int pa = (ga < M) ? 16 : 0;
            if (ga >= M) ga = M - 1;
            uint32_t da = smem_u32(&As[buf][row * SA_STR + c4 * 4]);
            CP16P(da, A + (size_t)ga * 1024u + k0 + c4 * 4, pa);
            uint32_t db = smem_u32(&Bs[buf][row * SA_STR + c4 * 4]);
            CP16(db, Bt + (size_t)(n0 + row) * 1024u + k0 + c4 * 4);
        }
        CP_COMMIT();
    };

    issue(0, 0);
    issue(1, 1);

    for (int kt = 0; kt < 64; kt++) {
        const int buf = kt & 1;
        if (kt < 63) CP_WAIT(1);
        else         CP_WAIT(0);
        __syncthreads();

#pragma unroll
        for (int ks = 0; ks < 2; ks++) {
            uint32_t af[4][4], bf[8][2];
#pragma unroll
            for (int i = 0; i < 4; i++) {
                const float* base = &As[buf][(wm + i * 16) * SA_STR + ks * 8];
                af[i][0] = __float_as_uint(base[(g)     * SA_STR + tg]);
                af[i][1] = __float_as_uint(base[(g + 8) * SA_STR + tg]);
                af[i][2] = __float_as_uint(base[(g)     * SA_STR + tg + 4]);
                af[i][3] = __float_as_uint(base[(g + 8) * SA_STR + tg + 4]);
            }
#pragma unroll
            for (int j = 0; j < 8; j++) {
                const float* base = &Bs[buf][(wn + j * 8 + g) * SA_STR + ks * 8];
                bf[j][0] = __float_as_uint(base[tg]);
                bf[j][1] = __float_as_uint(base[tg + 4]);
            }
#pragma unroll
            for (int i = 0; i < 4; i++)
#pragma unroll
                for (int j = 0; j < 8; j++)
                    MMA_TF32(d[i][j][0], d[i][j][1], d[i][j][2], d[i][j][3],
                             af[i][0], af[i][1], af[i][2], af[i][3],
                             bf[j][0], bf[j][1]);
        }
        __syncthreads();
        if (kt + 2 < 64) issue(buf, kt + 2);
    }

    int rs = 0, cs = 0;
    if (QPOST) {
        const int ci = cur[0] % 16;
        rs = ci % 4; cs = ci / 4;
    }

#pragma unroll
    for (int i = 0; i < 4; i++) {
        const int rA = m0 + wm + i * 16 + g;
        const int rB = rA + 8;
        int fobA = 0, fobB = 0;
        if (QPOST) {
            { const int s = rA & 255;
              fobA = (((rs * 16 + (s >> 4)) << 6) + (cs * 16 + (s & 15))) * 64; }
            { const int s = rB & 255;
              fobB = (((rs * 16 + (s >> 4)) << 6) + (cs * 16 + (s & 15))) * 64; }
        }
#pragma unroll
        for (int j = 0; j < 8; j++) {
            const int c  = n0 + wn + j * 8 + tg * 2;
            const int d0 = (wn + j * 8 + tg * 2) & 63;
            float2 v0 = make_float2(d[i][j][0], d[i][j][1]);
            float2 v1 = make_float2(d[i][j][2], d[i][j][3]);
            if (BIAS) {
                const float b0 = bias[c], b1 = bias[c + 1];
                v0.x += b0; v0.y += b1; v1.x += b0; v1.y += b1;
            }
            if (QPOST) {
                rot_pair(v0, 0.f, cf, sf, fobA + d0);
                rot_pair(v1, 0.f, cf, sf, fobB + d0);
                if (rA < M) *(__half2*)&Ch[(size_t)rA * 1024u + c] =
                    __floats2half2_rn(v0.x * SCALEf, v0.y * SCALEf);
                if (rB < M) *(__half2*)&Ch[(size_t)rB * 1024u + c] =
                    __floats2half2_rn(v1.x * SCALEf, v1.y * SCALEf);
            } else {
                if (rA < M) *(float2*)&C[(size_t)rA * 1024u + c] = v0;
                if (rB < M) *(float2*)&C[(size_t)rB * 1024u + c] = v1;
            }
        }
    }
}

// =================== fused flash attention (fp16 mma) ======================
// Q,K half [row][1024]; V half transposed [bh][d][KVP].  Accum fp32.
// smem byte offsets:
#define QH_O 0                         // 128 x 72 halves
#define KH_O (QH_O + 128*72*2)         // 64 x 72 halves
#define VT_O (KH_O + 64*72*2)          // 64 x 72 halves (rows = d)
#define PH_O (VT_O + 64*72*2)          // 128 x 72 halves
#define SS_O (PH_O + 128*72*2)         // 128 x 68 floats
#define MR_O (SS_O + 128*68*4)
#define LR_O (MR_O + 128*4)
#define AR_O (LR_O + 128*4)
#define FL_SMEM (AR_O + 128*4)         // 91648 bytes

#define NCHUNK ((KVn + 63) / 64)       // 34

__global__ __launch_bounds__(256, 2)
void flash_attn(const __half* __restrict__ Q, const __half* __restrict__ K,
                const __half* __restrict__ Vt, float* __restrict__ O)
{
    extern __shared__ char smc[];
    __half* QH = (__half*)(smc + QH_O);
    __half* KH = (__half*)(smc + KH_O);
    __half* VT = (__half*)(smc + VT_O);
    __half* PH = (__half*)(smc + PH_O);
    float*  SS = (float*)(smc + SS_O);
    float*  MR = (float*)(smc + MR_O);
    float*  LR = (float*)(smc + LR_O);
    float*  AR = (float*)(smc + AR_O);

    const int tid = threadIdx.x;
    const int wid = tid >> 5, lane = tid & 31;
    const int g = lane >> 2, tg = lane & 3;
    const int bh = blockIdx.y, b = bh >> 4, h = bh & 15;
    const int m0 = blockIdx.x * 128;

    const __half* Qb = Q + ((size_t)(b * SEQn + m0)) * 1024u + h * 64;
    const __half* Kb = K + ((size_t)b * KVn) * 1024u + h * 64;
    const __half* Vb = Vt + ((size_t)bh * 64) * KVP;

    // stage Q tile: 128 rows x 64 halves (8 x 16B chunks per row)
#pragma unroll
    for (int e = 0; e < 4; e++) {
        int idx = tid + e * 256;          // 0..1023
        int r = idx >> 3, c8 = (idx & 7) * 8;
        uint32_t dq = smem_u32(&QH[r * 72 + c8]);
        CP16(dq, Qb + (size_t)r * 1024u + c8);
    }
    CP_COMMIT();
    if (tid < 128) { MR[tid] = -1e30f; LR[tid] = 0.f; }

    float oacc[4][2][4];
#pragma unroll
    for (int i = 0; i < 4; i++)
#pragma unroll
        for (int j = 0; j < 2; j++)
#pragma unroll
            for (int q = 0; q < 4; q++) oacc[i][j][q] = 0.f;

    const int om = (wid >> 2) * 64;
    const int on = (wid & 3) * 16;

    for (int t = 0; t < NCHUNK; t++) {
        const int kv0 = t * 64;
        const int rows = (KVn - kv0 < 64) ? (KVn - kv0) : 64;

        // ---- load K (64x64h) + Vt (64x64h) chunk ----
#pragma unroll
        for (int e = 0; e < 4; e++) {
            int idx = tid + e * 256;          // 0..1023
            int r = (idx >> 3) & 63, c8 = (idx & 7) * 8;
            if (idx < 512) {
                int kvr = kv0 + r; if (kvr >= KVn) kvr = KVn - 1;
                uint32_t dk = smem_u32(&KH[r * 72 + c8]);
                CP16(dk, Kb + (size_t)kvr * 1024u + c8);
            } else {
                uint32_t dv = smem_u32(&VT[r * 72 + c8]);
                CP16(dv, Vb + (size_t)r * KVP + kv0 + c8);   // pad region is zero
            }
        }
        CP_COMMIT();
        CP_WAIT(0);
        __syncthreads();

        // ---- S = Q @ K^T  (fp16 mma, 4 k16 steps) ----
        float s[4][2][4];
#pragma unroll
        for (int i = 0; i < 4; i++)
#pragma unroll
            for (int j = 0; j < 2; j++)
#pragma unroll
                for (int q = 0; q < 4; q++) s[i][j][q] = 0.f;

#pragma unroll
        for (int ks = 0; ks < 4; ks++) {
            uint32_t af[4][4], bf[2][2];
#pragma unroll
            for (int i = 0; i < 4; i++) {
                const __half* base = &QH[(om + i * 16) * 72 + ks * 16];
                af[i][0] = *(const uint32_t*)&base[(g)     * 72 + 2 * tg];
                af[i][1] = *(const uint32_t*)&base[(g + 8) * 72 + 2 * tg];
                af[i][2] = *(const uint32_t*)&base[(g)     * 72 + 2 * tg + 8];
                af[i][3] = *(const uint32_t*)&base[(g + 8) * 72 + 2 * tg + 8];
            }
#pragma unroll
            for (int j = 0; j < 2; j++) {
                const __half* base = &KH[(on + j * 8 + g) * 72 + ks * 16];
                bf[j][0] = *(const uint32_t*)&base[2 * tg];
                bf[j][1] = *(const uint32_t*)&base[2 * tg + 8];
            }
#pragma unroll
            for (int i = 0; i < 4; i++)
#pragma unroll
                for (int j = 0; j < 2; j++)
                    MMA_F16(s[i][j][0], s[i][j][1], s[i][j][2], s[i][j][3],
                            af[i][0], af[i][1], af[i][2], af[i][3],
                            bf[j][0], bf[j][1]);
        }
        // write S fragments (fp32) to smem
#pragma unroll
        for (int i = 0; i < 4; i++) {
            const int r0 = om + i * 16 + g;
#pragma unroll
            for (int j = 0; j < 2; j++) {
                const int c = on + j * 8 + tg * 2;
                SS[r0 * 68 + c]           = s[i][j][0];
                SS[r0 * 68 + c + 1]       = s[i][j][1];
                SS[(r0 + 8) * 68 + c]     = s[i][j][2];
                SS[(r0 + 8) * 68 + c + 1] = s[i][j][3];
            }
        }
        __syncthreads();

        // ---- online softmax; write P as half2 ----
#pragma unroll 4
        for (int rr = 0; rr < 16; rr++) {
            const int r = wid * 16 + rr;
            const int c0 = lane * 2;
            float v0 = (c0     < rows) ? SS[r * 68 + c0]     : -1e30f;
            float v1 = (c0 + 1 < rows) ? SS[r * 68 + c0 + 1] : -1e30f;
            float mx = fmaxf(v0, v1);
#pragma unroll
            for (int o = 16; o; o >>= 1) mx = fmaxf(mx, __shfl_xor_sync(~0u, mx, o));
            const float mold = MR[r];
            const float mnew = fmaxf(mold, mx);
            // half-round P; sum l over the SAME rounded values
            __half h0 = __float2half_rn((c0     < rows) ? __expf(v0 - mnew) : 0.f);
            __half h1 = __float2half_rn((c0 + 1 < rows) ? __expf(v1 - mnew) : 0.f);
            *(__half2*)&PH[r * 72 + c0] = __halves2half2(h0, h1);
            float ls = __half2float(h0) + __half2float(h1);
#pragma unroll
            for (int o = 16; o; o >>= 1) ls += __shfl_xor_sync(~0u, ls, o);
            if (lane == 0) {
                const float al = __expf(mold - mnew);
                AR[r] = al;
                LR[r] = LR[r] * al + ls;
                MR[r] = mnew;
            }
        }
        __syncthreads();

        // ---- rescale O accumulators ----
#pragma unroll
        for (int i = 0; i < 4; i++) {
            const float a0 = AR[om + i * 16 + g];
            const float a1 = AR[om + i * 16 + g + 8];
#pragma unroll
            for (int j = 0; j < 2; j++) {
                oacc[i][j][0] *= a0; oacc[i][j][1] *= a0;
                oacc[i][j][2] *= a1; oacc[i][j][3] *= a1;
            }
        }

        // ---- O += P @ V  (fp16 mma; B = Vt rows are d, k-contiguous) ----
#pragma unroll
        for (int ks = 0; ks < 4; ks++) {
            uint32_t af[4][4], bf[2][2];
#pragma unroll
            for (int i = 0; i < 4; i++) {
                const __half* base = &PH[(om + i * 16) * 72 + ks * 16];
                af[i][0] = *(const uint32_t*)&base[(g)     * 72 + 2 * tg];
                af[i][1] = *(const uint32_t*)&base[(g + 8) * 72 + 2 * tg];
                af[i][2] = *(const uint32_t*)&base[(g)     * 72 + 2 * tg + 8];
                af[i][3] = *(const uint32_t*)&base[(g + 8) * 72 + 2 * tg + 8];
            }
#pragma unroll
            for (int j = 0; j < 2; j++) {
                const __half* base = &VT[(on + j * 8 + g) * 72 + ks * 16];
                bf[j][0] = *(const uint32_t*)&base[2 * tg];
                bf[j][1] = *(const uint32_t*)&base[2 * tg + 8];
            }
#pragma unroll
            for (int i = 0; i < 4; i++)
#pragma unroll
                for (int j = 0; j < 2; j++)
                    MMA_F16(oacc[i][j][0], oacc[i][j][1], oacc[i][j][2], oacc[i][j][3],
                            af[i][0], af[i][1], af[i][2], af[i][3],
                            bf[j][0], bf[j][1]);
        }
        __syncthreads();
    }

    // ---- epilogue: O / l, rna-round for tf32 out-projection ----
    float* Ob = O + ((size_t)(b * SEQn + m0)) * 1024u + h * 64;
#pragma unroll
    for (int i = 0; i < 4; i++) {
        const int r0 = om + i * 16 + g;
        const float li0 = 1.f / LR[r0];
        const float li1 = 1.f / LR[r0 + 8];
#pragma unroll
        for (int j = 0; j < 2; j++) {
            const int c = on + j * 8 + tg * 2;
            float2 v0 = make_float2(rna_tf32(oacc[i][j][0] * li0), rna_tf32(oacc[i][j][1] * li0));
            float2 v1 = make_float2(rna_tf32(oacc[i][j][2] * li1), rna_tf32(oacc[i][j][3] * li1));
            *(float2*)&Ob[(size_t)r0 * 1024u + c]       = v0;
            *(float2*)&Ob[(size_t)(r0 + 8) * 1024u + c] = v1;
        }
    }
}

// ---------------- weight transpose (fp32 rna / fp16 rn) --------------------
__global__ void transpose_1024(const float* __restrict__ W, float* __restrict__ Wt)
{
    __shared__ float t[32][33];
    const int bx = blockIdx.x * 32, by = blockIdx.y * 32;
    const int tx = threadIdx.x, ty = threadIdx.y;
#pragma unroll
    for (int i = 0; i < 4; i++)
        t[ty + i * 8][tx] = W[(size_t)(by + ty + i * 8) * 1024 + bx + tx];
    __syncthreads();
#pragma unroll
    for (int i = 0; i < 4; i++)
        Wt[(size_t)(bx + ty + i * 8) * 1024 + by + tx] = rna_tf32(t[tx][ty + i * 8]);
}

__global__ void transpose_1024_h(const float* __restrict__ W, __half* __restrict__ Wt)
{
    __shared__ float t[32][33];
    const int bx = blockIdx.x * 32, by = blockIdx.y * 32;
    const int tx = threadIdx.x, ty = threadIdx.y;
#pragma unroll
    for (int i = 0; i < 4; i++)
        t[ty + i * 8][tx] = W[(size_t)(by + ty + i * 8) * 1024 + bx + tx];
    __syncthreads();
#pragma unroll
    for (int i = 0; i < 4; i++)
        Wt[(size_t)(bx + ty + i * 8) * 1024 + by + tx] = __float2half_rn(t[tx][ty + i * 8]);
}

// ---------------- rounding / conversion copies -----------------------------
__global__ void round_copy(const float4* __restrict__ in, float4* __restrict__ out, int n4)
{
    int i = blockIdx.x * blockDim.x + threadIdx.x;
    if (i < n4) {
        float4 v = in[i];
        v.x = rna_tf32(v.x); v.y = rna_tf32(v.y);
        v.z = rna_tf32(v.z); v.w = rna_tf32(v.w);
        out[i] = v;
    }
}

__global__ void half_copy(const float4* __restrict__ in, __half2* __restrict__ out, int n4)
{
    int i = blockIdx.x * blockDim.x + threadIdx.x;
    if (i < n4) {
        float4 v = in[i];
        out[2 * i]     = __floats2half2_rn(v.x, v.y);
        out[2 * i + 1] = __floats2half2_rn(v.z, v.w);
    }
}

__global__ void cs_precompute(const float* __restrict__ freqs,
                              float* __restrict__ cf, float* __restrict__ sf)
{
    int i = blockIdx.x * blockDim.x + threadIdx.x;
    if (i < 64*64*64) {
        float v = freqs[i];
        cf[i] = cosf(v);
        sf[i] = sinf(v);
    }
}

// ---------------- host launch ----------------------------------------------
extern "C" void kernel_launch(void* const* d_in, const int* in_sizes, int n_in,
                              void* d_out, int out_size)
{
    const float* x     = (const float*)d_in[0];
    const float* cond  = (const float*)d_in[1];
    const float* freqs = (const float*)d_in[2];
    const float* Wq    = (const float*)d_in[3];
    const float* Wk    = (const float*)d_in[4];
    const float* Wv    = (const float*)d_in[5];
    const float* rel   = (const float*)d_in[6];
    const float* Wo    = (const float*)d_in[7];
    const float* bo    = (const float*)d_in[8];
    const int*   memi  = (const int*)d_in[9];
    const int*   cur   = (const int*)d_in[10];
    float* out = (float*)d_out;

    float *Ob, *Wt, *Xr, *Cf, *Sf;
    __half *Qh, *Kh, *Vt, *Whkv, *Ch;
    cudaGetSymbolAddress((void**)&Qh, g_Qh);
    cudaGetSymbolAddress((void**)&Kh, g_Kh);
    cudaGetSymbolAddress((void**)&Vt, g_Vt);
    cudaGetSymbolAddress((void**)&Ob, g_O);
    cudaGetSymbolAddress((void**)&Wt, g_Wt);
    cudaGetSymbolAddress((void**)&Xr, g_Xr);
    cudaGetSymbolAddress((void**)&Cf, g_cosf);
    cudaGetSymbolAddress((void**)&Sf, g_sinf);
    cudaGetSymbolAddress((void**)&Whkv, g_Whkv);
    cudaGetSymbolAddress((void**)&Ch, g_Ch);

    cudaFuncSetAttribute(flash_attn, cudaFuncAttributeMaxDynamicSharedMemorySize, FL_SMEM);

    float* Wtq = Wt;
    float* Wto = Wt + (size_t)DIMn * INNERn;

    // prep
    half_copy<<<(ROWS_C*DIMn/4 + 255)/256, 256>>>((const float4*)cond, (__half2*)Ch, ROWS_C*DIMn/4);
    round_copy<<<(ROWS_X*DIMn/4 + 255)/256, 256>>>((const float4*)x, (float4*)Xr, ROWS_X*DIMn/4);
    cs_precompute<<<(64*64*64 + 255)/256, 256>>>(freqs, Cf, Sf);
    transpose_1024_h<<<dim3(32,32), dim3(32,8)>>>(Wk, Whkv);
    transpose_1024_h<<<dim3(32,32), dim3(32,8)>>>(Wv, Whkv + (size_t)DIMn * INNERn);
    transpose_1024<<<dim3(32,32), dim3(32,8)>>>(Wq, Wtq);
    transpose_1024<<<dim3(32,32), dim3(32,8)>>>(Wo, Wto);

    // merged K|V projection on fp16 tensor cores
    // K: bias+rotary -> half.  V: -> transposed half.
    gemm_kv_f16<<<dim3(16, 266), 128>>>(Ch, Whkv, Kh, Vt, Cf, Sf, rel, memi, cur, ROWS_C);

    // Q projection (tf32); fused rotary + scale -> half
    gemm_mma<false,true><<<dim3(8, 32), 128>>>(Xr, Wtq, nullptr, Qh, nullptr, Cf, Sf, cur, ROWS_X);

    // fused flash attention (fp16 mma)
    flash_attn<<<dim3(2, BHn), 256, FL_SMEM>>>(Qh, Kh, Vt, Ob);

    // out = O @ Wo + bo (tf32)
    gemm_mma<true,false><<<dim3(8, 32), 128>>>(Ob, Wto, out, nullptr, bo, nullptr, nullptr, nullptr, ROWS_X);
}